// round 1
// baseline (speedup 1.0000x reference)
#include <cuda_runtime.h>
#include <cuda_bf16.h>
#include <math.h>

// Problem constants
#define BNN   2048          // total nodes (B*N)
#define FF    768           // feature dim
#define EE    65536         // edges
#define BB    8             // batch
#define LLQ   64            // query length
#define NREL  3
#define NBINS (BNN*NREL)    // 6144
#define K4    3072          // concat K for rgcn gemm
#define K2    1536          // concat K for alpha gemm

// ------------------------- device scratch -------------------------
__device__ int   g_bin_cnt[NBINS];
__device__ int   g_bin_off[NBINS];
__device__ int   g_cursor[NBINS];
__device__ float g_inv_cnt[NBINS];
__device__ int   g_sorted_src[EE];
__device__ float g_X4[(size_t)BNN * K4];     // [x|agg0|agg1|agg2]
__device__ float g_Wcat[(size_t)K4 * FF];    // [W_root; W_rel0; W_rel1; W_rel2]
__device__ float g_H[(size_t)BNN * K2];      // [h | qi]
__device__ float g_HG[(size_t)BNN * FF];     // hg
__device__ float g_QG[(size_t)BB * LLQ * FF];// qg

__device__ __forceinline__ float sigmoidf_(float x) {
    return __fdividef(1.0f, 1.0f + __expf(-x));
}

// ------------------------- CSR build -------------------------
__global__ void k_zero_bins() {
    int i = blockIdx.x * blockDim.x + threadIdx.x;
    if (i < NBINS) g_bin_cnt[i] = 0;
}

__global__ void k_hist(const int* __restrict__ ei, const int* __restrict__ et) {
    int i = blockIdx.x * blockDim.x + threadIdx.x;
    if (i < EE) {
        int dst = ei[EE + i];
        int key = dst * NREL + et[i];
        atomicAdd(&g_bin_cnt[key], 1);
    }
}

// single CTA (1024 threads), 6 bins per thread: exclusive scan + cursor + inv_cnt
__global__ void k_scan() {
    __shared__ int wsum[32];
    int t = threadIdx.x;
    int c[6], loc[6];
    int s = 0;
#pragma unroll
    for (int j = 0; j < 6; ++j) { c[j] = g_bin_cnt[t * 6 + j]; loc[j] = s; s += c[j]; }
    int lane = t & 31, w = t >> 5;
    int v = s;
#pragma unroll
    for (int d = 1; d < 32; d <<= 1) { int u = __shfl_up_sync(0xffffffffu, v, d); if (lane >= d) v += u; }
    if (lane == 31) wsum[w] = v;
    __syncthreads();
    if (w == 0) {
        int u = wsum[lane];
#pragma unroll
        for (int d = 1; d < 32; d <<= 1) { int z = __shfl_up_sync(0xffffffffu, u, d); if (lane >= d) u += z; }
        wsum[lane] = u;
    }
    __syncthreads();
    int base = (w > 0 ? wsum[w - 1] : 0) + (v - s);
#pragma unroll
    for (int j = 0; j < 6; ++j) {
        int idx = t * 6 + j;
        int off = base + loc[j];
        g_bin_off[idx] = off;
        g_cursor[idx]  = off;
        g_inv_cnt[idx] = 1.0f / (float)(c[j] > 0 ? c[j] : 1);
    }
}

__global__ void k_fill(const int* __restrict__ ei, const int* __restrict__ et) {
    int i = blockIdx.x * blockDim.x + threadIdx.x;
    if (i < EE) {
        int dst = ei[EE + i];
        int key = dst * NREL + et[i];
        int pos = atomicAdd(&g_cursor[key], 1);
        g_sorted_src[pos] = ei[i];
    }
}

// ------------------------- copies -------------------------
// x [2048,768] -> X4[:, 0:768]
__global__ void k_copy_x(const float4* __restrict__ src) {
    int i = blockIdx.x * blockDim.x + threadIdx.x;   // over 2048*192
    if (i < BNN * 192) {
        int row = i / 192, c = i - row * 192;
        reinterpret_cast<float4*>(g_X4)[(size_t)row * 768 + c] = src[(size_t)row * 192 + c];
    }
}

// Wcat = [W_root (768x768); W_rel (2304x768)]
__global__ void k_copy_w(const float4* __restrict__ Wroot, const float4* __restrict__ Wrel) {
    int i = blockIdx.x * blockDim.x + threadIdx.x;   // over 3072*192
    if (i < K4 * 192) {
        int k = i / 192, c = i - k * 192;
        float4 v = (k < FF) ? Wroot[(size_t)k * 192 + c]
                            : Wrel[(size_t)(k - FF) * 192 + c];
        reinterpret_cast<float4*>(g_Wcat)[i] = v;
    }
}

// ------------------------- aggregation -------------------------
// one CTA per (dst, rel) bin; 192 threads, float4 each; reads X4[:, :768], writes X4[:, (rel+1)*768 ..]
__global__ void __launch_bounds__(192) k_aggregate() {
    int bin = blockIdx.x;
    int dst = bin / NREL;
    int rel = bin - dst * NREL;
    int beg = g_bin_off[bin];
    int cnt = g_bin_cnt[bin];
    int t = threadIdx.x;
    const float4* x4 = reinterpret_cast<const float4*>(g_X4);
    float4 acc = make_float4(0.f, 0.f, 0.f, 0.f);
    for (int j = 0; j < cnt; ++j) {
        int s = g_sorted_src[beg + j];
        float4 v = x4[(size_t)s * 768 + t];
        acc.x += v.x; acc.y += v.y; acc.z += v.z; acc.w += v.w;
    }
    float ic = g_inv_cnt[bin];
    acc.x *= ic; acc.y *= ic; acc.z *= ic; acc.w *= ic;
    reinterpret_cast<float4*>(g_X4)[(size_t)dst * 768 + (size_t)(rel + 1) * 192 + t] = acc;
}

// ------------------------- GEMM -------------------------
// C[M,N] = A[M,K] @ op(B); TRANSB=0: B[K,N] row-major; TRANSB=1: B as Bt[N,K] row-major.
// Tiles: 64x64, BK=16, 128 threads, 8x4 per thread.
// EPI: 0 none, 1 +bias, 2 relu(+bias), 3 gate: a=sig(v+bias); out=a*tanh(qi)+(1-a)*h
template<int TRANSB, int EPI>
__global__ void __launch_bounds__(128) k_gemm(
    const float* __restrict__ A, int lda,
    const float* __restrict__ B, int ldb,
    float* __restrict__ C, int ldc,
    int K,
    const float* __restrict__ bias,
    const float* __restrict__ Hbuf)
{
    __shared__ float As[16][68];
    __shared__ float Bs[16][68];
    int tid = threadIdx.x;
    int m0 = blockIdx.y * 64;
    int n0 = blockIdx.x * 64;

    float acc[8][4];
#pragma unroll
    for (int i = 0; i < 8; ++i)
#pragma unroll
        for (int j = 0; j < 4; ++j) acc[i][j] = 0.f;

    int idx0 = tid * 2, idx1 = tid * 2 + 1;
    int ar0 = idx0 >> 2, ac0 = (idx0 & 3) * 4;
    int ar1 = idx1 >> 2, ac1 = (idx1 & 3) * 4;
    int br0 = idx0 >> 4, bc0 = (idx0 & 15) * 4;
    int br1 = idx1 >> 4, bc1 = (idx1 & 15) * 4;

    int tm0 = (tid >> 4) * 8;
    int tn0 = (tid & 15) * 4;

    for (int k0 = 0; k0 < K; k0 += 16) {
        float4 a0 = *reinterpret_cast<const float4*>(A + (size_t)(m0 + ar0) * lda + k0 + ac0);
        float4 a1 = *reinterpret_cast<const float4*>(A + (size_t)(m0 + ar1) * lda + k0 + ac1);
        float4 b0, b1;
        if (TRANSB) {
            b0 = *reinterpret_cast<const float4*>(B + (size_t)(n0 + ar0) * ldb + k0 + ac0);
            b1 = *reinterpret_cast<const float4*>(B + (size_t)(n0 + ar1) * ldb + k0 + ac1);
        } else {
            b0 = *reinterpret_cast<const float4*>(B + (size_t)(k0 + br0) * ldb + n0 + bc0);
            b1 = *reinterpret_cast<const float4*>(B + (size_t)(k0 + br1) * ldb + n0 + bc1);
        }
        __syncthreads();
        As[ac0 + 0][ar0] = a0.x; As[ac0 + 1][ar0] = a0.y; As[ac0 + 2][ar0] = a0.z; As[ac0 + 3][ar0] = a0.w;
        As[ac1 + 0][ar1] = a1.x; As[ac1 + 1][ar1] = a1.y; As[ac1 + 2][ar1] = a1.z; As[ac1 + 3][ar1] = a1.w;
        if (TRANSB) {
            Bs[ac0 + 0][ar0] = b0.x; Bs[ac0 + 1][ar0] = b0.y; Bs[ac0 + 2][ar0] = b0.z; Bs[ac0 + 3][ar0] = b0.w;
            Bs[ac1 + 0][ar1] = b1.x; Bs[ac1 + 1][ar1] = b1.y; Bs[ac1 + 2][ar1] = b1.z; Bs[ac1 + 3][ar1] = b1.w;
        } else {
            *reinterpret_cast<float4*>(&Bs[br0][bc0]) = b0;
            *reinterpret_cast<float4*>(&Bs[br1][bc1]) = b1;
        }
        __syncthreads();
#pragma unroll
        for (int kk = 0; kk < 16; ++kk) {
            float4 av0 = *reinterpret_cast<const float4*>(&As[kk][tm0]);
            float4 av1 = *reinterpret_cast<const float4*>(&As[kk][tm0 + 4]);
            float4 bv  = *reinterpret_cast<const float4*>(&Bs[kk][tn0]);
            float a[8] = {av0.x, av0.y, av0.z, av0.w, av1.x, av1.y, av1.z, av1.w};
            float bb[4] = {bv.x, bv.y, bv.z, bv.w};
#pragma unroll
            for (int i = 0; i < 8; ++i)
#pragma unroll
                for (int j = 0; j < 4; ++j)
                    acc[i][j] = fmaf(a[i], bb[j], acc[i][j]);
        }
    }

    float4 bias4 = make_float4(0.f, 0.f, 0.f, 0.f);
    if (EPI >= 1) bias4 = *reinterpret_cast<const float4*>(bias + n0 + tn0);

#pragma unroll
    for (int i = 0; i < 8; ++i) {
        int row = m0 + tm0 + i;
        float4 v = make_float4(acc[i][0], acc[i][1], acc[i][2], acc[i][3]);
        if (EPI == 1) {
            v.x += bias4.x; v.y += bias4.y; v.z += bias4.z; v.w += bias4.w;
        } else if (EPI == 2) {
            v.x = fmaxf(v.x + bias4.x, 0.f); v.y = fmaxf(v.y + bias4.y, 0.f);
            v.z = fmaxf(v.z + bias4.z, 0.f); v.w = fmaxf(v.w + bias4.w, 0.f);
        } else if (EPI == 3) {
            const float* hp  = Hbuf + (size_t)row * K2 + n0 + tn0;
            const float* qip = hp + FF;
            float4 h4  = *reinterpret_cast<const float4*>(hp);
            float4 qi4 = *reinterpret_cast<const float4*>(qip);
            float a;
            a = sigmoidf_(v.x + bias4.x); v.x = a * tanhf(qi4.x) + (1.f - a) * h4.x;
            a = sigmoidf_(v.y + bias4.y); v.y = a * tanhf(qi4.y) + (1.f - a) * h4.y;
            a = sigmoidf_(v.z + bias4.z); v.z = a * tanhf(qi4.z) + (1.f - a) * h4.z;
            a = sigmoidf_(v.w + bias4.w); v.w = a * tanhf(qi4.w) + (1.f - a) * h4.w;
        }
        *reinterpret_cast<float4*>(C + (size_t)row * ldc + n0 + tn0) = v;
    }
}

// ------------------------- fused qi -------------------------
// qi[b,n,f] = sum_l sigmoid(hg[b,n,f]+qg[b,l,f]) * q[b,l,f]
// sigmoid(a+b) = 1/(1 + e^{-a} e^{-b}); e^{-qg} kept in 64 registers per thread.
// grid: (fb=8, nq=4, b=8), 96 threads (one f each). writes H[:, 768:1536].
__global__ void __launch_bounds__(96) k_qi(const float* __restrict__ q) {
    int fb = blockIdx.x;
    int nq = blockIdx.y;
    int b  = blockIdx.z;
    int t  = threadIdx.x;
    int f  = fb * 96 + t;

    __shared__ float qs[LLQ * 96];
    float eq[LLQ];
#pragma unroll
    for (int l = 0; l < LLQ; ++l) {
        size_t qidx = ((size_t)(b * LLQ + l)) * FF + f;
        float qgv = g_QG[qidx];
        qgv = fminf(fmaxf(qgv, -60.f), 60.f);
        eq[l] = __expf(-qgv);
        qs[l * 96 + t] = q[qidx];
    }
    __syncthreads();

    int n0 = nq * 64;
    for (int n = n0; n < n0 + 64; ++n) {
        int node = b * 256 + n;
        float hgv = g_HG[(size_t)node * FF + f];
        hgv = fminf(fmaxf(hgv, -60.f), 60.f);
        float eh = __expf(-hgv);
        float acc = 0.f;
#pragma unroll
        for (int l = 0; l < LLQ; ++l) {
            float d = fmaf(eh, eq[l], 1.0f);
            float s = __fdividef(1.0f, d);
            acc = fmaf(s, qs[l * 96 + t], acc);
        }
        g_H[(size_t)node * K2 + FF + f] = acc;
    }
}

// ------------------------- host -------------------------
extern "C" void kernel_launch(void* const* d_in, const int* in_sizes, int n_in,
                              void* d_out, int out_size) {
    const float* x     = (const float*)d_in[0];
    const int*   ei    = (const int*)  d_in[1];
    const int*   et    = (const int*)  d_in[2];
    const float* q     = (const float*)d_in[3];
    const float* Wrel1 = (const float*)d_in[4];
    const float* Wrt1  = (const float*)d_in[5];
    const float* b1    = (const float*)d_in[6];
    const float* Wrel2 = (const float*)d_in[7];
    const float* Wrt2  = (const float*)d_in[8];
    const float* b2    = (const float*)d_in[9];
    const float* Wg    = (const float*)d_in[10];
    const float* bg    = (const float*)d_in[11];
    const float* Wq    = (const float*)d_in[12];
    const float* bq    = (const float*)d_in[13];
    float* out = (float*)d_out;

    float *pX4, *pWcat, *pH, *pHG, *pQG;
    cudaGetSymbolAddress((void**)&pX4,  g_X4);
    cudaGetSymbolAddress((void**)&pWcat,g_Wcat);
    cudaGetSymbolAddress((void**)&pH,   g_H);
    cudaGetSymbolAddress((void**)&pHG,  g_HG);
    cudaGetSymbolAddress((void**)&pQG,  g_QG);

    // ---- CSR build (shared by both layers) ----
    k_zero_bins<<<(NBINS + 255) / 256, 256>>>();
    k_hist<<<EE / 256, 256>>>(ei, et);
    k_scan<<<1, 1024>>>();
    k_fill<<<EE / 256, 256>>>(ei, et);

    dim3 gBig(FF / 64, BNN / 64);   // 12 x 32
    dim3 gQg (FF / 64, (BB * LLQ) / 64); // 12 x 8

    // ---- layer 1: RGCN ----
    k_copy_x<<<(BNN * 192 + 255) / 256, 256>>>((const float4*)x);
    k_copy_w<<<(K4 * 192 + 255) / 256, 256>>>((const float4*)Wrt1, (const float4*)Wrel1);
    k_aggregate<<<NBINS, 192>>>();
    k_gemm<0, 2><<<gBig, 128>>>(pX4, K4, pWcat, FF, pH, K2, K4, b1, nullptr);

    // ---- gate 1 ----
    k_gemm<1, 0><<<gBig, 128>>>(pH, K2, Wg, 2 * FF, pHG, FF, FF, nullptr, nullptr);
    k_gemm<1, 1><<<gQg, 128>>>(q, FF, Wg + FF, 2 * FF, pQG, FF, FF, bg, nullptr); // qg (reused by gate 2)
    k_qi<<<dim3(8, 4, 8), 96>>>(q);
    k_gemm<1, 3><<<gBig, 128>>>(pH, K2, Wq, 2 * FF, pX4, K4, K2, bq, pH); // h' -> X4[:, :768]

    // ---- layer 2: RGCN ----
    k_copy_w<<<(K4 * 192 + 255) / 256, 256>>>((const float4*)Wrt2, (const float4*)Wrel2);
    k_aggregate<<<NBINS, 192>>>();
    k_gemm<0, 2><<<gBig, 128>>>(pX4, K4, pWcat, FF, pH, K2, K4, b2, nullptr);

    // ---- gate 2 ----
    k_gemm<1, 0><<<gBig, 128>>>(pH, K2, Wg, 2 * FF, pHG, FF, FF, nullptr, nullptr);
    k_qi<<<dim3(8, 4, 8), 96>>>(q);
    k_gemm<1, 3><<<gBig, 128>>>(pH, K2, Wq, 2 * FF, out, FF, K2, bq, pH);
}

// round 3
// speedup vs baseline: 2.2245x; 2.2245x over previous
#include <cuda_runtime.h>
#include <cstdint>
#include <math.h>

// Problem constants
#define BNN   2048
#define FF    768
#define EE    65536
#define BB    8
#define LLQ   64
#define NREL  3
#define NBINS (BNN*NREL)
#define K4    3072
#define K2    1536

// ------------------------- device scratch -------------------------
__device__ int   g_bin_cnt[NBINS];
__device__ int   g_bin_off[NBINS];
__device__ int   g_cursor[NBINS];
__device__ float g_inv_cnt[NBINS];
__device__ int   g_sorted_src[EE];
__device__ float g_X4[(size_t)BNN * K4];      // [x|agg0|agg1|agg2]
__device__ float g_WcatT[(size_t)FF * K4];    // transposed [N=768, K=3072]
__device__ float g_H[(size_t)BNN * K2];       // [h | qi]
__device__ float g_HG[(size_t)BNN * FF];      // hg
__device__ float g_QG[(size_t)BB * LLQ * FF]; // qg

__device__ __forceinline__ float sigmoidf_(float x) {
    return __fdividef(1.0f, 1.0f + __expf(-x));
}
__device__ __forceinline__ float tanh_fast(float x) {
    float e = __expf(2.0f * x);
    return 1.0f - __fdividef(2.0f, e + 1.0f);
}
__device__ __forceinline__ float to_tf32(float x) {
    uint32_t u;
    asm("cvt.rna.tf32.f32 %0, %1;" : "=r"(u) : "f"(x));
    return __uint_as_float(u);
}

#define MMA_TF32(D, Aa, Bb) \
    asm volatile("mma.sync.aligned.m16n8k8.row.col.f32.tf32.tf32.f32 " \
        "{%0,%1,%2,%3}, {%4,%5,%6,%7}, {%8,%9}, {%0,%1,%2,%3};" \
        : "+f"((D)[0]), "+f"((D)[1]), "+f"((D)[2]), "+f"((D)[3]) \
        : "r"((Aa)[0]), "r"((Aa)[1]), "r"((Aa)[2]), "r"((Aa)[3]), \
          "r"((Bb)[0]), "r"((Bb)[1]))

// ------------------------- CSR build -------------------------
__global__ void k_zero_bins() {
    int i = blockIdx.x * blockDim.x + threadIdx.x;
    if (i < NBINS) g_bin_cnt[i] = 0;
}

__global__ void k_hist(const int* __restrict__ ei, const int* __restrict__ et) {
    int i = blockIdx.x * blockDim.x + threadIdx.x;
    if (i < EE) {
        int dst = ei[EE + i];
        atomicAdd(&g_bin_cnt[dst * NREL + et[i]], 1);
    }
}

__global__ void k_scan() {
    __shared__ int wsum[32];
    int t = threadIdx.x;
    int c[6], loc[6];
    int s = 0;
#pragma unroll
    for (int j = 0; j < 6; ++j) { c[j] = g_bin_cnt[t * 6 + j]; loc[j] = s; s += c[j]; }
    int lane = t & 31, w = t >> 5;
    int v = s;
#pragma unroll
    for (int d = 1; d < 32; d <<= 1) { int u = __shfl_up_sync(0xffffffffu, v, d); if (lane >= d) v += u; }
    if (lane == 31) wsum[w] = v;
    __syncthreads();
    if (w == 0) {
        int u = wsum[lane];
#pragma unroll
        for (int d = 1; d < 32; d <<= 1) { int z = __shfl_up_sync(0xffffffffu, u, d); if (lane >= d) u += z; }
        wsum[lane] = u;
    }
    __syncthreads();
    int base = (w > 0 ? wsum[w - 1] : 0) + (v - s);
#pragma unroll
    for (int j = 0; j < 6; ++j) {
        int idx = t * 6 + j;
        int off = base + loc[j];
        g_bin_off[idx] = off;
        g_cursor[idx]  = off;
        g_inv_cnt[idx] = 1.0f / (float)(c[j] > 0 ? c[j] : 1);
    }
}

__global__ void k_fill(const int* __restrict__ ei, const int* __restrict__ et) {
    int i = blockIdx.x * blockDim.x + threadIdx.x;
    if (i < EE) {
        int dst = ei[EE + i];
        int pos = atomicAdd(&g_cursor[dst * NREL + et[i]], 1);
        g_sorted_src[pos] = ei[i];
    }
}

// ------------------------- copies -------------------------
__global__ void k_copy_x(const float4* __restrict__ src) {
    int i = blockIdx.x * blockDim.x + threadIdx.x;
    if (i < BNN * 192) {
        int row = i / 192, c = i - row * 192;
        reinterpret_cast<float4*>(g_X4)[(size_t)row * 768 + c] = src[(size_t)row * 192 + c];
    }
}

// WcatT[n][k] = (k<768 ? Wroot[k][n] : Wrel_flat[k-768][n]); tiled transpose
__global__ void __launch_bounds__(256) k_transpose_w(
    const float* __restrict__ Wroot, const float* __restrict__ Wrel) {
    __shared__ float t[32][33];
    int kb = blockIdx.x * 32, nb = blockIdx.y * 32;
    int tx = threadIdx.x, ty = threadIdx.y;   // block (32, 8)
#pragma unroll
    for (int j = 0; j < 4; ++j) {
        int k = kb + ty + j * 8;
        float v = (k < FF) ? Wroot[(size_t)k * FF + nb + tx]
                           : Wrel[(size_t)(k - FF) * FF + nb + tx];
        t[ty + j * 8][tx] = v;
    }
    __syncthreads();
#pragma unroll
    for (int j = 0; j < 4; ++j) {
        int n = nb + ty + j * 8;
        g_WcatT[(size_t)n * K4 + kb + tx] = t[tx][ty + j * 8];
    }
}

// ------------------------- aggregation -------------------------
__global__ void __launch_bounds__(192) k_aggregate() {
    int bin = blockIdx.x;
    int dst = bin / NREL;
    int rel = bin - dst * NREL;
    int beg = g_bin_off[bin];
    int cnt = g_bin_cnt[bin];
    int t = threadIdx.x;
    const float4* x4 = reinterpret_cast<const float4*>(g_X4);
    float4 acc = make_float4(0.f, 0.f, 0.f, 0.f);
    for (int j = 0; j < cnt; ++j) {
        int s = g_sorted_src[beg + j];
        float4 v = x4[(size_t)s * 768 + t];
        acc.x += v.x; acc.y += v.y; acc.z += v.z; acc.w += v.w;
    }
    float ic = g_inv_cnt[bin];
    acc.x *= ic; acc.y *= ic; acc.z *= ic; acc.w *= ic;
    reinterpret_cast<float4*>(g_X4)[(size_t)dst * 768 + (size_t)(rel + 1) * 192 + t] = acc;
}

// ------------------------- tf32 mma.sync GEMM -------------------------
// D[M,N] = A[M,K] @ B[N,K]^T, fp32 in/out, tf32 MMA (HMMA), fp32 accumulate.
// CTA tile 64x64, K-step 32, 128 threads (4 warps, each 32x32).
// EPI: 0 none, 1 +bias, 2 relu(+bias), 3 gate (a=sig(v+bias); a*tanh(qi)+(1-a)*h)
template<int EPI>
__global__ void __launch_bounds__(128) k_mma(
    const float* __restrict__ A, int lda,
    const float* __restrict__ B, int ldb,
    float* __restrict__ C, int ldc,
    int K,
    const float* __restrict__ bias,
    const float* __restrict__ Hbuf)
{
    __shared__ float As[64][36];   // pad 4 -> conflict-free fragment LDS
    __shared__ float Bs[64][36];
    const int tid = threadIdx.x;
    const int m0 = blockIdx.y * 64;
    const int n0 = blockIdx.x * 64;
    const int wid = tid >> 5, lane = tid & 31;
    const int wm = (wid >> 1) * 32;
    const int wn = (wid & 1) * 32;
    const int g = lane >> 2, t = lane & 3;

    const int lr = tid >> 3;          // 0..15 (row base within 16-row slab)
    const int lc = (tid & 7) * 4;     // float col 0..28

    float d[2][4][4];
#pragma unroll
    for (int mt = 0; mt < 2; ++mt)
#pragma unroll
        for (int nt = 0; nt < 4; ++nt)
#pragma unroll
            for (int j = 0; j < 4; ++j) d[mt][nt][j] = 0.f;

    float4 pa[4], pb[4];
#pragma unroll
    for (int i = 0; i < 4; ++i) {
        pa[i] = *reinterpret_cast<const float4*>(A + (size_t)(m0 + lr + i * 16) * lda + lc);
        pb[i] = *reinterpret_cast<const float4*>(B + (size_t)(n0 + lr + i * 16) * ldb + lc);
    }

    const int nk = K >> 5;
    for (int c = 0; c < nk; ++c) {
        __syncthreads();
#pragma unroll
        for (int i = 0; i < 4; ++i) {
            int r = lr + i * 16;
            As[r][lc + 0] = to_tf32(pa[i].x); As[r][lc + 1] = to_tf32(pa[i].y);
            As[r][lc + 2] = to_tf32(pa[i].z); As[r][lc + 3] = to_tf32(pa[i].w);
            Bs[r][lc + 0] = to_tf32(pb[i].x); Bs[r][lc + 1] = to_tf32(pb[i].y);
            Bs[r][lc + 2] = to_tf32(pb[i].z); Bs[r][lc + 3] = to_tf32(pb[i].w);
        }
        __syncthreads();
        if (c + 1 < nk) {
            int k0 = (c + 1) << 5;
#pragma unroll
            for (int i = 0; i < 4; ++i) {
                pa[i] = *reinterpret_cast<const float4*>(A + (size_t)(m0 + lr + i * 16) * lda + k0 + lc);
                pb[i] = *reinterpret_cast<const float4*>(B + (size_t)(n0 + lr + i * 16) * ldb + k0 + lc);
            }
        }
#pragma unroll
        for (int ks = 0; ks < 4; ++ks) {
            uint32_t af[2][4], bf[4][2];
            int kc = ks * 8 + t;
#pragma unroll
            for (int mt = 0; mt < 2; ++mt) {
                int r = wm + mt * 16 + g;
                af[mt][0] = __float_as_uint(As[r][kc]);
                af[mt][1] = __float_as_uint(As[r + 8][kc]);
                af[mt][2] = __float_as_uint(As[r][kc + 4]);
                af[mt][3] = __float_as_uint(As[r + 8][kc + 4]);
            }
#pragma unroll
            for (int nt = 0; nt < 4; ++nt) {
                int rn = wn + nt * 8 + g;
                bf[nt][0] = __float_as_uint(Bs[rn][kc]);
                bf[nt][1] = __float_as_uint(Bs[rn][kc + 4]);
            }
#pragma unroll
            for (int mt = 0; mt < 2; ++mt)
#pragma unroll
                for (int nt = 0; nt < 4; ++nt)
                    MMA_TF32(d[mt][nt], af[mt], bf[nt]);
        }
    }

    // Epilogue: c0,c1 -> (row g, cols 2t,2t+1); c2,c3 -> (row g+8, same cols)
#pragma unroll
    for (int mt = 0; mt < 2; ++mt)
#pragma unroll
        for (int nt = 0; nt < 4; ++nt) {
            int cc = n0 + wn + nt * 8 + t * 2;
            float2 bb = make_float2(0.f, 0.f);
            if (EPI >= 1) bb = *reinterpret_cast<const float2*>(bias + cc);
#pragma unroll
            for (int h = 0; h < 2; ++h) {
                int r = m0 + wm + mt * 16 + g + h * 8;
                float2 v = make_float2(d[mt][nt][h * 2 + 0], d[mt][nt][h * 2 + 1]);
                if (EPI >= 1) { v.x += bb.x; v.y += bb.y; }
                if (EPI == 2) {
                    v.x = fmaxf(v.x, 0.f); v.y = fmaxf(v.y, 0.f);
                } else if (EPI == 3) {
                    const float* hp = Hbuf + (size_t)r * K2 + cc;
                    float2 h2  = *reinterpret_cast<const float2*>(hp);
                    float2 qi2 = *reinterpret_cast<const float2*>(hp + FF);
                    float a;
                    a = sigmoidf_(v.x); v.x = a * tanh_fast(qi2.x) + (1.f - a) * h2.x;
                    a = sigmoidf_(v.y); v.y = a * tanh_fast(qi2.y) + (1.f - a) * h2.y;
                }
                *reinterpret_cast<float2*>(C + (size_t)r * ldc + cc) = v;
            }
        }
}

// ------------------------- fused qi -------------------------
__global__ void __launch_bounds__(96) k_qi(const float* __restrict__ q) {
    int fb = blockIdx.x;
    int nq = blockIdx.y;
    int b  = blockIdx.z;
    int t  = threadIdx.x;
    int f  = fb * 96 + t;

    __shared__ float qs[LLQ * 96];
    float eq[LLQ];
#pragma unroll
    for (int l = 0; l < LLQ; ++l) {
        size_t qidx = ((size_t)(b * LLQ + l)) * FF + f;
        float qgv = g_QG[qidx];
        qgv = fminf(fmaxf(qgv, -60.f), 60.f);
        eq[l] = __expf(-qgv);
        qs[l * 96 + t] = q[qidx];
    }
    __syncthreads();

    int n0 = nq * 64;
    for (int n = n0; n < n0 + 64; ++n) {
        int node = b * 256 + n;
        float hgv = g_HG[(size_t)node * FF + f];
        hgv = fminf(fmaxf(hgv, -60.f), 60.f);
        float eh = __expf(-hgv);
        float acc = 0.f;
#pragma unroll
        for (int l = 0; l < LLQ; ++l) {
            float dd = fmaf(eh, eq[l], 1.0f);
            float s = __fdividef(1.0f, dd);
            acc = fmaf(s, qs[l * 96 + t], acc);
        }
        g_H[(size_t)node * K2 + FF + f] = acc;
    }
}

// ------------------------- host -------------------------
extern "C" void kernel_launch(void* const* d_in, const int* in_sizes, int n_in,
                              void* d_out, int out_size) {
    const float* x     = (const float*)d_in[0];
    const int*   ei    = (const int*)  d_in[1];
    const int*   et    = (const int*)  d_in[2];
    const float* q     = (const float*)d_in[3];
    const float* Wrel1 = (const float*)d_in[4];
    const float* Wrt1  = (const float*)d_in[5];
    const float* b1    = (const float*)d_in[6];
    const float* Wrel2 = (const float*)d_in[7];
    const float* Wrt2  = (const float*)d_in[8];
    const float* b2    = (const float*)d_in[9];
    const float* Wg    = (const float*)d_in[10];
    const float* bg    = (const float*)d_in[11];
    const float* Wq    = (const float*)d_in[12];
    const float* bq    = (const float*)d_in[13];
    float* out = (float*)d_out;

    float *pX4, *pWT, *pH, *pHG, *pQG;
    cudaGetSymbolAddress((void**)&pX4, g_X4);
    cudaGetSymbolAddress((void**)&pWT, g_WcatT);
    cudaGetSymbolAddress((void**)&pH,  g_H);
    cudaGetSymbolAddress((void**)&pHG, g_HG);
    cudaGetSymbolAddress((void**)&pQG, g_QG);

    // ---- CSR build ----
    k_zero_bins<<<(NBINS + 255) / 256, 256>>>();
    k_hist<<<EE / 256, 256>>>(ei, et);
    k_scan<<<1, 1024>>>();
    k_fill<<<EE / 256, 256>>>(ei, et);

    dim3 gBig(FF / 64, BNN / 64);            // 12 x 32 = 384 CTAs
    dim3 gQg (FF / 64, (BB * LLQ) / 64);     // 12 x 8
    dim3 gTr (K4 / 32, FF / 32);
    dim3 bTr (32, 8);

    // ---- layer 1: RGCN ----
    k_copy_x<<<(BNN * 192 + 255) / 256, 256>>>((const float4*)x);
    k_transpose_w<<<gTr, bTr>>>(Wrt1, Wrel1);
    k_aggregate<<<NBINS, 192>>>();
    k_mma<2><<<gBig, 128>>>(pX4, K4, pWT, K4, pH, K2, K4, b1, nullptr);

    // ---- gate 1 ----
    k_mma<0><<<gBig, 128>>>(pH, K2, Wg, 2 * FF, pHG, FF, FF, nullptr, nullptr);
    k_mma<1><<<gQg, 128>>>(q, FF, Wg + FF, 2 * FF, pQG, FF, FF, bg, nullptr);
    k_qi<<<dim3(8, 4, 8), 96>>>(q);
    k_mma<3><<<gBig, 128>>>(pH, K2, Wq, 2 * FF, pX4, K4, K2, bq, pH);

    // ---- layer 2: RGCN ----
    k_transpose_w<<<gTr, bTr>>>(Wrt2, Wrel2);
    k_aggregate<<<NBINS, 192>>>();
    k_mma<2><<<gBig, 128>>>(pX4, K4, pWT, K4, pH, K2, K4, b2, nullptr);

    // ---- gate 2 ----
    k_mma<0><<<gBig, 128>>>(pH, K2, Wg, 2 * FF, pHG, FF, FF, nullptr, nullptr);
    k_qi<<<dim3(8, 4, 8), 96>>>(q);
    k_mma<3><<<gBig, 128>>>(pH, K2, Wq, 2 * FF, out, FF, K2, bq, pH);
}

// round 4
// speedup vs baseline: 2.3259x; 1.0456x over previous
#include <cuda_runtime.h>
#include <cstdint>
#include <math.h>

// Problem constants
#define BNN   2048
#define FF    768
#define EE    65536
#define BB    8
#define LLQ   64
#define NREL  3
#define NBINS (BNN*NREL)
#define K4    3072
#define K2    1536

// ------------------------- device scratch -------------------------
__device__ int   g_bin_cnt[NBINS];
__device__ int   g_bin_off[NBINS];
__device__ int   g_cursor[NBINS];
__device__ float g_inv_cnt[NBINS];
__device__ int   g_sorted_src[EE];
__device__ float g_X4[(size_t)BNN * K4];      // [x|agg0|agg1|agg2]  (tf32-rounded)
__device__ float g_WcatT[(size_t)FF * K4];    // transposed weights  (tf32-rounded)
__device__ float g_H[(size_t)BNN * K2];       // [h | qi]            (tf32-rounded)
__device__ float g_HG[(size_t)BNN * FF];      // hg (full fp32)
__device__ float g_QG[(size_t)BB * LLQ * FF]; // qg (full fp32)
__device__ float g_Wgr[(size_t)FF * 2 * FF];  // rounded Wg
__device__ float g_Wqr[(size_t)FF * 2 * FF];  // rounded Wq
__device__ float g_qr[(size_t)BB * LLQ * FF]; // rounded q

__device__ __forceinline__ float sigmoidf_(float x) {
    return __fdividef(1.0f, 1.0f + __expf(-x));
}
__device__ __forceinline__ float tanh_fast(float x) {
    float e = __expf(2.0f * x);
    return 1.0f - __fdividef(2.0f, e + 1.0f);
}
__device__ __forceinline__ float to_tf32(float x) {
    uint32_t u;
    asm("cvt.rna.tf32.f32 %0, %1;" : "=r"(u) : "f"(x));
    return __uint_as_float(u);
}
__device__ __forceinline__ float4 r4(float4 v) {
    return make_float4(to_tf32(v.x), to_tf32(v.y), to_tf32(v.z), to_tf32(v.w));
}
__device__ __forceinline__ uint32_t smem_u32(const void* p) {
    uint32_t a;
    asm("{ .reg .u64 t; cvta.to.shared.u64 t, %1; cvt.u32.u64 %0, t; }" : "=r"(a) : "l"(p));
    return a;
}
__device__ __forceinline__ void cp16(uint32_t dst, const void* src) {
    asm volatile("cp.async.cg.shared.global [%0], [%1], 16;" :: "r"(dst), "l"(src));
}
#define CP_COMMIT() asm volatile("cp.async.commit_group;" ::: "memory")
#define CP_WAIT1()  asm volatile("cp.async.wait_group 1;" ::: "memory")
#define CP_WAIT0()  asm volatile("cp.async.wait_group 0;" ::: "memory")

#define MMA_TF32(D, Aa, Bb) \
    asm volatile("mma.sync.aligned.m16n8k8.row.col.f32.tf32.tf32.f32 " \
        "{%0,%1,%2,%3}, {%4,%5,%6,%7}, {%8,%9}, {%0,%1,%2,%3};" \
        : "+f"((D)[0]), "+f"((D)[1]), "+f"((D)[2]), "+f"((D)[3]) \
        : "r"((Aa)[0]), "r"((Aa)[1]), "r"((Aa)[2]), "r"((Aa)[3]), \
          "r"((Bb)[0]), "r"((Bb)[1]))

// ------------------------- CSR build -------------------------
__global__ void k_zero_bins() {
    int i = blockIdx.x * blockDim.x + threadIdx.x;
    if (i < NBINS) g_bin_cnt[i] = 0;
}

__global__ void k_hist(const int* __restrict__ ei, const int* __restrict__ et) {
    int i = blockIdx.x * blockDim.x + threadIdx.x;
    if (i < EE) {
        int dst = ei[EE + i];
        atomicAdd(&g_bin_cnt[dst * NREL + et[i]], 1);
    }
}

__global__ void k_scan() {
    __shared__ int wsum[32];
    int t = threadIdx.x;
    int c[6], loc[6];
    int s = 0;
#pragma unroll
    for (int j = 0; j < 6; ++j) { c[j] = g_bin_cnt[t * 6 + j]; loc[j] = s; s += c[j]; }
    int lane = t & 31, w = t >> 5;
    int v = s;
#pragma unroll
    for (int d = 1; d < 32; d <<= 1) { int u = __shfl_up_sync(0xffffffffu, v, d); if (lane >= d) v += u; }
    if (lane == 31) wsum[w] = v;
    __syncthreads();
    if (w == 0) {
        int u = wsum[lane];
#pragma unroll
        for (int d = 1; d < 32; d <<= 1) { int z = __shfl_up_sync(0xffffffffu, u, d); if (lane >= d) u += z; }
        wsum[lane] = u;
    }
    __syncthreads();
    int base = (w > 0 ? wsum[w - 1] : 0) + (v - s);
#pragma unroll
    for (int j = 0; j < 6; ++j) {
        int idx = t * 6 + j;
        int off = base + loc[j];
        g_bin_off[idx] = off;
        g_cursor[idx]  = off;
        g_inv_cnt[idx] = 1.0f / (float)(c[j] > 0 ? c[j] : 1);
    }
}

__global__ void k_fill(const int* __restrict__ ei, const int* __restrict__ et) {
    int i = blockIdx.x * blockDim.x + threadIdx.x;
    if (i < EE) {
        int dst = ei[EE + i];
        int pos = atomicAdd(&g_cursor[dst * NREL + et[i]], 1);
        g_sorted_src[pos] = ei[i];
    }
}

// ------------------------- copies (tf32-rounding producers) -------------------------
__global__ void k_copy_x(const float4* __restrict__ src) {
    int i = blockIdx.x * blockDim.x + threadIdx.x;
    if (i < BNN * 192) {
        int row = i / 192, c = i - row * 192;
        reinterpret_cast<float4*>(g_X4)[(size_t)row * 768 + c] = r4(src[(size_t)row * 192 + c]);
    }
}

__global__ void k_round4(const float4* __restrict__ src, float4* __restrict__ dst, int n4) {
    int i = blockIdx.x * blockDim.x + threadIdx.x;
    if (i < n4) dst[i] = r4(src[i]);
}

// WcatT[n][k] = (k<768 ? Wroot[k][n] : Wrel_flat[k-768][n]); tiled transpose + round
__global__ void __launch_bounds__(256) k_transpose_w(
    const float* __restrict__ Wroot, const float* __restrict__ Wrel) {
    __shared__ float t[32][33];
    int kb = blockIdx.x * 32, nb = blockIdx.y * 32;
    int tx = threadIdx.x, ty = threadIdx.y;   // block (32, 8)
#pragma unroll
    for (int j = 0; j < 4; ++j) {
        int k = kb + ty + j * 8;
        float v = (k < FF) ? Wroot[(size_t)k * FF + nb + tx]
                           : Wrel[(size_t)(k - FF) * FF + nb + tx];
        t[ty + j * 8][tx] = to_tf32(v);
    }
    __syncthreads();
#pragma unroll
    for (int j = 0; j < 4; ++j) {
        int n = nb + ty + j * 8;
        g_WcatT[(size_t)n * K4 + kb + tx] = t[tx][ty + j * 8];
    }
}

// ------------------------- aggregation -------------------------
__global__ void __launch_bounds__(192) k_aggregate() {
    int bin = blockIdx.x;
    int dst = bin / NREL;
    int rel = bin - dst * NREL;
    int beg = g_bin_off[bin];
    int cnt = g_bin_cnt[bin];
    int t = threadIdx.x;
    const float4* x4 = reinterpret_cast<const float4*>(g_X4);
    float4 acc = make_float4(0.f, 0.f, 0.f, 0.f);
    for (int j = 0; j < cnt; ++j) {
        int s = g_sorted_src[beg + j];
        float4 v = x4[(size_t)s * 768 + t];
        acc.x += v.x; acc.y += v.y; acc.z += v.z; acc.w += v.w;
    }
    float ic = g_inv_cnt[bin];
    acc.x *= ic; acc.y *= ic; acc.z *= ic; acc.w *= ic;
    reinterpret_cast<float4*>(g_X4)[(size_t)dst * 768 + (size_t)(rel + 1) * 192 + t] = r4(acc);
}

// ------------------------- tf32 mma.sync GEMM (cp.async, 3-stage) -------------------------
// D[M,N] = A[M,K] @ B[N,K]^T. Operands are pre-rounded tf32 bit patterns.
// CTA tile 64x64, K-chunk 32, 128 threads (4 warps, each 32x32).
// EPI: 0 none, 1 +bias, 2 relu(+bias)+round, 3 gate+round, 4 gate(no round)
#define SM_STAGE 4608                 // floats per stage (2 x 64 x 36)
#define SMEM_MMA_BYTES (3 * SM_STAGE * 4)

template<int EPI>
__global__ void __launch_bounds__(128) k_mma(
    const float* __restrict__ A, int lda,
    const float* __restrict__ B, int ldb,
    float* __restrict__ C, int ldc,
    int K,
    const float* __restrict__ bias,
    const float* __restrict__ Hbuf)
{
    extern __shared__ float sm[];
    const int tid = threadIdx.x;
    const int m0 = blockIdx.y * 64;
    const int n0 = blockIdx.x * 64;
    const int wid = tid >> 5, lane = tid & 31;
    const int wm = (wid >> 1) * 32;
    const int wn = (wid & 1) * 32;
    const int g = lane >> 2, t = lane & 3;
    const int lr = tid >> 3;          // 0..15
    const int lc = (tid & 7) * 4;     // 0..28

    const uint32_t smb = smem_u32(sm);
    const uint32_t soff = ((uint32_t)lr * 36 + (uint32_t)lc) * 4u;

    float d[2][4][4];
#pragma unroll
    for (int mt = 0; mt < 2; ++mt)
#pragma unroll
        for (int nt = 0; nt < 4; ++nt)
#pragma unroll
            for (int j = 0; j < 4; ++j) d[mt][nt][j] = 0.f;

    const int nk = K >> 5;
    const float* Abase = A + (size_t)(m0 + lr) * lda + lc;
    const float* Bbase = B + (size_t)(n0 + lr) * ldb + lc;

    auto issue = [&](int c) {
        int s = c - (c / 3) * 3;
        uint32_t as_ = smb + (uint32_t)s * (SM_STAGE * 4) + soff;
        uint32_t bs_ = as_ + 2304 * 4;
        int k0 = c << 5;
#pragma unroll
        for (int i = 0; i < 4; ++i) {
            cp16(as_ + (uint32_t)i * (16 * 36 * 4), Abase + (size_t)i * 16 * lda + k0);
            cp16(bs_ + (uint32_t)i * (16 * 36 * 4), Bbase + (size_t)i * 16 * ldb + k0);
        }
        CP_COMMIT();
    };

    issue(0);
    if (nk > 1) issue(1);

    for (int c = 0; c < nk; ++c) {
        if (c + 1 < nk) CP_WAIT1(); else CP_WAIT0();
        __syncthreads();
        if (c + 2 < nk) issue(c + 2);

        int s = c - (c / 3) * 3;
        const float* As_ = sm + s * SM_STAGE;
        const float* Bs_ = As_ + 2304;

#pragma unroll
        for (int ks = 0; ks < 4; ++ks) {
            uint32_t af[2][4], bf[4][2];
            int kc = ks * 8 + t;
#pragma unroll
            for (int mt = 0; mt < 2; ++mt) {
                int r = wm + mt * 16 + g;
                af[mt][0] = __float_as_uint(As_[r * 36 + kc]);
                af[mt][1] = __float_as_uint(As_[(r + 8) * 36 + kc]);
                af[mt][2] = __float_as_uint(As_[r * 36 + kc + 4]);
                af[mt][3] = __float_as_uint(As_[(r + 8) * 36 + kc + 4]);
            }
#pragma unroll
            for (int nt = 0; nt < 4; ++nt) {
                int rn = wn + nt * 8 + g;
                bf[nt][0] = __float_as_uint(Bs_[rn * 36 + kc]);
                bf[nt][1] = __float_as_uint(Bs_[rn * 36 + kc + 4]);
            }
#pragma unroll
            for (int mt = 0; mt < 2; ++mt)
#pragma unroll
                for (int nt = 0; nt < 4; ++nt)
                    MMA_TF32(d[mt][nt], af[mt], bf[nt]);
        }
        __syncthreads();
    }

    // Epilogue: c0,c1 -> (row g, cols 2t,2t+1); c2,c3 -> (row g+8)
#pragma unroll
    for (int mt = 0; mt < 2; ++mt)
#pragma unroll
        for (int nt = 0; nt < 4; ++nt) {
            int cc = n0 + wn + nt * 8 + t * 2;
            float2 bb = make_float2(0.f, 0.f);
            if (EPI >= 1) bb = *reinterpret_cast<const float2*>(bias + cc);
#pragma unroll
            for (int h = 0; h < 2; ++h) {
                int r = m0 + wm + mt * 16 + g + h * 8;
                float2 v = make_float2(d[mt][nt][h * 2 + 0], d[mt][nt][h * 2 + 1]);
                if (EPI >= 1) { v.x += bb.x; v.y += bb.y; }
                if (EPI == 2) {
                    v.x = to_tf32(fmaxf(v.x, 0.f)); v.y = to_tf32(fmaxf(v.y, 0.f));
                } else if (EPI == 3 || EPI == 4) {
                    const float* hp = Hbuf + (size_t)r * K2 + cc;
                    float2 h2  = *reinterpret_cast<const float2*>(hp);
                    float2 qi2 = *reinterpret_cast<const float2*>(hp + FF);
                    float a;
                    a = sigmoidf_(v.x); v.x = a * tanh_fast(qi2.x) + (1.f - a) * h2.x;
                    a = sigmoidf_(v.y); v.y = a * tanh_fast(qi2.y) + (1.f - a) * h2.y;
                    if (EPI == 3) { v.x = to_tf32(v.x); v.y = to_tf32(v.y); }
                }
                *reinterpret_cast<float2*>(C + (size_t)r * ldc + cc) = v;
            }
        }
}

// ------------------------- fused qi -------------------------
__global__ void __launch_bounds__(96) k_qi(const float* __restrict__ q) {
    int fb = blockIdx.x;
    int nq = blockIdx.y;
    int b  = blockIdx.z;
    int t  = threadIdx.x;
    int f  = fb * 96 + t;

    __shared__ float qs[LLQ * 96];
    float eq[LLQ];
#pragma unroll
    for (int l = 0; l < LLQ; ++l) {
        size_t qidx = ((size_t)(b * LLQ + l)) * FF + f;
        float qgv = g_QG[qidx];
        qgv = fminf(fmaxf(qgv, -60.f), 60.f);
        eq[l] = __expf(-qgv);
        qs[l * 96 + t] = q[qidx];
    }
    __syncthreads();

    int n0 = nq * 64;
    for (int n = n0; n < n0 + 64; ++n) {
        int node = b * 256 + n;
        float hgv = g_HG[(size_t)node * FF + f];
        hgv = fminf(fmaxf(hgv, -60.f), 60.f);
        float eh = __expf(-hgv);
        float acc = 0.f;
#pragma unroll
        for (int l = 0; l < LLQ; ++l) {
            float dd = fmaf(eh, eq[l], 1.0f);
            float s = __fdividef(1.0f, dd);
            acc = fmaf(s, qs[l * 96 + t], acc);
        }
        g_H[(size_t)node * K2 + FF + f] = to_tf32(acc);
    }
}

// ------------------------- host -------------------------
extern "C" void kernel_launch(void* const* d_in, const int* in_sizes, int n_in,
                              void* d_out, int out_size) {
    const float* x     = (const float*)d_in[0];
    const int*   ei    = (const int*)  d_in[1];
    const int*   et    = (const int*)  d_in[2];
    const float* q     = (const float*)d_in[3];
    const float* Wrel1 = (const float*)d_in[4];
    const float* Wrt1  = (const float*)d_in[5];
    const float* b1    = (const float*)d_in[6];
    const float* Wrel2 = (const float*)d_in[7];
    const float* Wrt2  = (const float*)d_in[8];
    const float* b2    = (const float*)d_in[9];
    const float* Wg    = (const float*)d_in[10];
    const float* bg    = (const float*)d_in[11];
    const float* Wq    = (const float*)d_in[12];
    const float* bq    = (const float*)d_in[13];
    float* out = (float*)d_out;

    float *pX4, *pWT, *pH, *pHG, *pQG, *pWgr, *pWqr, *pqr;
    cudaGetSymbolAddress((void**)&pX4,  g_X4);
    cudaGetSymbolAddress((void**)&pWT,  g_WcatT);
    cudaGetSymbolAddress((void**)&pH,   g_H);
    cudaGetSymbolAddress((void**)&pHG,  g_HG);
    cudaGetSymbolAddress((void**)&pQG,  g_QG);
    cudaGetSymbolAddress((void**)&pWgr, g_Wgr);
    cudaGetSymbolAddress((void**)&pWqr, g_Wqr);
    cudaGetSymbolAddress((void**)&pqr,  g_qr);

    cudaFuncSetAttribute(k_mma<0>, cudaFuncAttributeMaxDynamicSharedMemorySize, SMEM_MMA_BYTES);
    cudaFuncSetAttribute(k_mma<1>, cudaFuncAttributeMaxDynamicSharedMemorySize, SMEM_MMA_BYTES);
    cudaFuncSetAttribute(k_mma<2>, cudaFuncAttributeMaxDynamicSharedMemorySize, SMEM_MMA_BYTES);
    cudaFuncSetAttribute(k_mma<3>, cudaFuncAttributeMaxDynamicSharedMemorySize, SMEM_MMA_BYTES);
    cudaFuncSetAttribute(k_mma<4>, cudaFuncAttributeMaxDynamicSharedMemorySize, SMEM_MMA_BYTES);

    // ---- CSR build ----
    k_zero_bins<<<(NBINS + 255) / 256, 256>>>();
    k_hist<<<EE / 256, 256>>>(ei, et);
    k_scan<<<1, 1024>>>();
    k_fill<<<EE / 256, 256>>>(ei, et);

    // ---- pre-round raw GEMM operands ----
    int nWg4 = FF * 2 * FF / 4, nq4 = BB * LLQ * FF / 4;
    k_round4<<<(nWg4 + 255) / 256, 256>>>((const float4*)Wg, (float4*)pWgr, nWg4);
    k_round4<<<(nWg4 + 255) / 256, 256>>>((const float4*)Wq, (float4*)pWqr, nWg4);
    k_round4<<<(nq4 + 255) / 256, 256>>>((const float4*)q, (float4*)pqr, nq4);

    dim3 gBig(FF / 64, BNN / 64);            // 12 x 32 = 384 CTAs
    dim3 gQg (FF / 64, (BB * LLQ) / 64);     // 12 x 8
    dim3 gTr (K4 / 32, FF / 32);
    dim3 bTr (32, 8);

    // ---- layer 1: RGCN ----
    k_copy_x<<<(BNN * 192 + 255) / 256, 256>>>((const float4*)x);
    k_transpose_w<<<gTr, bTr>>>(Wrt1, Wrel1);
    k_aggregate<<<NBINS, 192>>>();
    k_mma<2><<<gBig, 128, SMEM_MMA_BYTES>>>(pX4, K4, pWT, K4, pH, K2, K4, b1, nullptr);

    // ---- gate 1 ----
    k_mma<0><<<gBig, 128, SMEM_MMA_BYTES>>>(pH, K2, pWgr, 2 * FF, pHG, FF, FF, nullptr, nullptr);
    k_mma<1><<<gQg, 128, SMEM_MMA_BYTES>>>(pqr, FF, pWgr + FF, 2 * FF, pQG, FF, FF, bg, nullptr);
    k_qi<<<dim3(8, 4, 8), 96>>>(q);
    k_mma<3><<<gBig, 128, SMEM_MMA_BYTES>>>(pH, K2, pWqr, 2 * FF, pX4, K4, K2, bq, pH);

    // ---- layer 2: RGCN ----
    k_transpose_w<<<gTr, bTr>>>(Wrt2, Wrel2);
    k_aggregate<<<NBINS, 192>>>();
    k_mma<2><<<gBig, 128, SMEM_MMA_BYTES>>>(pX4, K4, pWT, K4, pH, K2, K4, b2, nullptr);

    // ---- gate 2 ----
    k_mma<0><<<gBig, 128, SMEM_MMA_BYTES>>>(pH, K2, pWgr, 2 * FF, pHG, FF, FF, nullptr, nullptr);
    k_qi<<<dim3(8, 4, 8), 96>>>(q);
    k_mma<4><<<gBig, 128, SMEM_MMA_BYTES>>>(pH, K2, pWqr, 2 * FF, out, FF, K2, bq, pH);
}

// round 5
// speedup vs baseline: 2.3578x; 1.0137x over previous
#include <cuda_runtime.h>
#include <cstdint>
#include <math.h>

// Problem constants
#define BNN   2048
#define FF    768
#define EE    65536
#define BB    8
#define LLQ   64
#define NREL  3
#define NBINS (BNN*NREL)
#define K4    3072
#define K2    1536

// ------------------------- device scratch -------------------------
__device__ int   g_bin_cnt[NBINS];
__device__ int   g_bin_off[NBINS];
__device__ int   g_cursor[NBINS];
__device__ float g_inv_cnt[NBINS];
__device__ int   g_sorted_src[EE];
__device__ float g_X4[(size_t)BNN * K4];      // [x|agg0|agg1|agg2]  (tf32-rounded)
__device__ float g_WcatT[(size_t)FF * K4];    // transposed weights  (tf32-rounded)
__device__ float g_H[(size_t)BNN * K2];       // [h | qi]            (tf32-rounded)
__device__ float g_HG[(size_t)BNN * FF];      // hg (full fp32)
__device__ float g_QG[(size_t)BB * LLQ * FF]; // qg (full fp32)
__device__ float g_Wgr[(size_t)FF * 2 * FF];  // rounded Wg
__device__ float g_Wqr[(size_t)FF * 2 * FF];  // rounded Wq
__device__ float g_qr[(size_t)BB * LLQ * FF]; // rounded q

__device__ __forceinline__ float sigmoidf_(float x) {
    return __fdividef(1.0f, 1.0f + __expf(-x));
}
__device__ __forceinline__ float tanh_fast(float x) {
    float e = __expf(2.0f * x);
    return 1.0f - __fdividef(2.0f, e + 1.0f);
}
__device__ __forceinline__ float to_tf32(float x) {
    uint32_t u;
    asm("cvt.rna.tf32.f32 %0, %1;" : "=r"(u) : "f"(x));
    return __uint_as_float(u);
}
__device__ __forceinline__ float4 r4(float4 v) {
    return make_float4(to_tf32(v.x), to_tf32(v.y), to_tf32(v.z), to_tf32(v.w));
}
__device__ __forceinline__ uint32_t smem_u32(const void* p) {
    uint32_t a;
    asm("{ .reg .u64 t; cvta.to.shared.u64 t, %1; cvt.u32.u64 %0, t; }" : "=r"(a) : "l"(p));
    return a;
}
__device__ __forceinline__ void cp16(uint32_t dst, const void* src) {
    asm volatile("cp.async.cg.shared.global [%0], [%1], 16;" :: "r"(dst), "l"(src));
}
#define CP_COMMIT() asm volatile("cp.async.commit_group;" ::: "memory")
#define CP_WAIT2()  asm volatile("cp.async.wait_group 2;" ::: "memory")
#define CP_WAIT1()  asm volatile("cp.async.wait_group 1;" ::: "memory")
#define CP_WAIT0()  asm volatile("cp.async.wait_group 0;" ::: "memory")

#define MMA_TF32(D, Aa, Bb) \
    asm volatile("mma.sync.aligned.m16n8k8.row.col.f32.tf32.tf32.f32 " \
        "{%0,%1,%2,%3}, {%4,%5,%6,%7}, {%8,%9}, {%0,%1,%2,%3};" \
        : "+f"((D)[0]), "+f"((D)[1]), "+f"((D)[2]), "+f"((D)[3]) \
        : "r"((Aa)[0]), "r"((Aa)[1]), "r"((Aa)[2]), "r"((Aa)[3]), \
          "r"((Bb)[0]), "r"((Bb)[1]))

// ------------------------- CSR build -------------------------
__global__ void k_zero_bins() {
    int i = blockIdx.x * blockDim.x + threadIdx.x;
    if (i < NBINS) g_bin_cnt[i] = 0;
}

__global__ void k_hist(const int* __restrict__ ei, const int* __restrict__ et) {
    int i = blockIdx.x * blockDim.x + threadIdx.x;
    if (i < EE) {
        int dst = ei[EE + i];
        atomicAdd(&g_bin_cnt[dst * NREL + et[i]], 1);
    }
}

__global__ void k_scan() {
    __shared__ int wsum[32];
    int t = threadIdx.x;
    int c[6], loc[6];
    int s = 0;
#pragma unroll
    for (int j = 0; j < 6; ++j) { c[j] = g_bin_cnt[t * 6 + j]; loc[j] = s; s += c[j]; }
    int lane = t & 31, w = t >> 5;
    int v = s;
#pragma unroll
    for (int d = 1; d < 32; d <<= 1) { int u = __shfl_up_sync(0xffffffffu, v, d); if (lane >= d) v += u; }
    if (lane == 31) wsum[w] = v;
    __syncthreads();
    if (w == 0) {
        int u = wsum[lane];
#pragma unroll
        for (int d = 1; d < 32; d <<= 1) { int z = __shfl_up_sync(0xffffffffu, u, d); if (lane >= d) u += z; }
        wsum[lane] = u;
    }
    __syncthreads();
    int base = (w > 0 ? wsum[w - 1] : 0) + (v - s);
#pragma unroll
    for (int j = 0; j < 6; ++j) {
        int idx = t * 6 + j;
        int off = base + loc[j];
        g_bin_off[idx] = off;
        g_cursor[idx]  = off;
        g_inv_cnt[idx] = 1.0f / (float)(c[j] > 0 ? c[j] : 1);
    }
}

__global__ void k_fill(const int* __restrict__ ei, const int* __restrict__ et) {
    int i = blockIdx.x * blockDim.x + threadIdx.x;
    if (i < EE) {
        int dst = ei[EE + i];
        int pos = atomicAdd(&g_cursor[dst * NREL + et[i]], 1);
        g_sorted_src[pos] = ei[i];
    }
}

// ------------------------- copies (tf32-rounding producers) -------------------------
__global__ void k_copy_x(const float4* __restrict__ src) {
    int i = blockIdx.x * blockDim.x + threadIdx.x;
    if (i < BNN * 192) {
        int row = i / 192, c = i - row * 192;
        reinterpret_cast<float4*>(g_X4)[(size_t)row * 768 + c] = r4(src[(size_t)row * 192 + c]);
    }
}

__global__ void k_round4(const float4* __restrict__ src, float4* __restrict__ dst, int n4) {
    int i = blockIdx.x * blockDim.x + threadIdx.x;
    if (i < n4) dst[i] = r4(src[i]);
}

// WcatT[n][k] = (k<768 ? Wroot[k][n] : Wrel_flat[k-768][n]); tiled transpose + round
__global__ void __launch_bounds__(256) k_transpose_w(
    const float* __restrict__ Wroot, const float* __restrict__ Wrel) {
    __shared__ float t[32][33];
    int kb = blockIdx.x * 32, nb = blockIdx.y * 32;
    int tx = threadIdx.x, ty = threadIdx.y;   // block (32, 8)
#pragma unroll
    for (int j = 0; j < 4; ++j) {
        int k = kb + ty + j * 8;
        float v = (k < FF) ? Wroot[(size_t)k * FF + nb + tx]
                           : Wrel[(size_t)(k - FF) * FF + nb + tx];
        t[ty + j * 8][tx] = to_tf32(v);
    }
    __syncthreads();
#pragma unroll
    for (int j = 0; j < 4; ++j) {
        int n = nb + ty + j * 8;
        g_WcatT[(size_t)n * K4 + kb + tx] = t[tx][ty + j * 8];
    }
}

// ------------------------- aggregation -------------------------
__global__ void __launch_bounds__(192) k_aggregate() {
    int bin = blockIdx.x;
    int dst = bin / NREL;
    int rel = bin - dst * NREL;
    int beg = g_bin_off[bin];
    int cnt = g_bin_cnt[bin];
    int t = threadIdx.x;
    const float4* x4 = reinterpret_cast<const float4*>(g_X4);
    float4 acc = make_float4(0.f, 0.f, 0.f, 0.f);
    int sNext = (cnt > 0) ? g_sorted_src[beg] : 0;
    for (int j = 0; j < cnt; ++j) {
        int s = sNext;
        if (j + 1 < cnt) sNext = g_sorted_src[beg + j + 1];
        float4 v = x4[(size_t)s * 768 + t];
        acc.x += v.x; acc.y += v.y; acc.z += v.z; acc.w += v.w;
    }
    float ic = g_inv_cnt[bin];
    acc.x *= ic; acc.y *= ic; acc.z *= ic; acc.w *= ic;
    reinterpret_cast<float4*>(g_X4)[(size_t)dst * 768 + (size_t)(rel + 1) * 192 + t] = r4(acc);
}

// ------------------------- tf32 mma.sync GEMM (cp.async, 4-stage, 1 bar/chunk) ----
// D[M,N] = A[M,K] @ B[N,K]^T. Operands are pre-rounded tf32 bit patterns.
// CTA tile 64x64, K-chunk 32, 128 threads (4 warps, each 32x32).
// EPI: 0 none, 1 +bias, 2 relu(+bias)+round, 3 gate+round, 4 gate(no round)
#define SM_STAGE 4608                 // floats per stage (2 x 64 x 36)
#define SMEM_MMA_BYTES (4 * SM_STAGE * 4)

template<int EPI>
__global__ void __launch_bounds__(128) k_mma(
    const float* __restrict__ A, int lda,
    const float* __restrict__ B, int ldb,
    float* __restrict__ C, int ldc,
    int K,
    const float* __restrict__ bias,
    const float* __restrict__ Hbuf)
{
    extern __shared__ float sm[];
    const int tid = threadIdx.x;
    const int m0 = blockIdx.y * 64;
    const int n0 = blockIdx.x * 64;
    const int wid = tid >> 5, lane = tid & 31;
    const int wm = (wid >> 1) * 32;
    const int wn = (wid & 1) * 32;
    const int g = lane >> 2, t = lane & 3;
    const int lr = tid >> 3;          // 0..15
    const int lc = (tid & 7) * 4;     // 0..28

    const uint32_t smb = smem_u32(sm);
    const uint32_t soff = ((uint32_t)lr * 36 + (uint32_t)lc) * 4u;

    float d[2][4][4];
#pragma unroll
    for (int mt = 0; mt < 2; ++mt)
#pragma unroll
        for (int nt = 0; nt < 4; ++nt)
#pragma unroll
            for (int j = 0; j < 4; ++j) d[mt][nt][j] = 0.f;

    const int nk = K >> 5;
    const float* Abase = A + (size_t)(m0 + lr) * lda + lc;
    const float* Bbase = B + (size_t)(n0 + lr) * ldb + lc;

    auto issue = [&](int c) {
        int s = c & 3;
        uint32_t as_ = smb + (uint32_t)s * (SM_STAGE * 4) + soff;
        uint32_t bs_ = as_ + 2304 * 4;
        int k0 = c << 5;
#pragma unroll
        for (int i = 0; i < 4; ++i) {
            cp16(as_ + (uint32_t)i * (16 * 36 * 4), Abase + (size_t)i * 16 * lda + k0);
            cp16(bs_ + (uint32_t)i * (16 * 36 * 4), Bbase + (size_t)i * 16 * ldb + k0);
        }
        CP_COMMIT();
    };

    issue(0);
    if (nk > 1) issue(1);
    if (nk > 2) issue(2);

    for (int c = 0; c < nk; ++c) {
        int rem = nk - 1 - c;
        if (rem >= 2) CP_WAIT2();
        else if (rem == 1) CP_WAIT1();
        else CP_WAIT0();
        __syncthreads();
        if (c + 3 < nk) issue(c + 3);

        const float* As_ = sm + (c & 3) * SM_STAGE;
        const float* Bs_ = As_ + 2304;

#pragma unroll
        for (int ks = 0; ks < 4; ++ks) {
            uint32_t af[2][4], bf[4][2];
            int kc = ks * 8 + t;
#pragma unroll
            for (int mt = 0; mt < 2; ++mt) {
                int r = wm + mt * 16 + g;
                af[mt][0] = __float_as_uint(As_[r * 36 + kc]);
                af[mt][1] = __float_as_uint(As_[(r + 8) * 36 + kc]);
                af[mt][2] = __float_as_uint(As_[r * 36 + kc + 4]);
                af[mt][3] = __float_as_uint(As_[(r + 8) * 36 + kc + 4]);
            }
#pragma unroll
            for (int nt = 0; nt < 4; ++nt) {
                int rn = wn + nt * 8 + g;
                bf[nt][0] = __float_as_uint(Bs_[rn * 36 + kc]);
                bf[nt][1] = __float_as_uint(Bs_[rn * 36 + kc + 4]);
            }
#pragma unroll
            for (int mt = 0; mt < 2; ++mt)
#pragma unroll
                for (int nt = 0; nt < 4; ++nt)
                    MMA_TF32(d[mt][nt], af[mt], bf[nt]);
        }
        // no trailing __syncthreads: the top-of-loop barrier of chunk c+1
        // both publishes chunk c+1 data and retires stage (c-1)&3 for reuse.
    }

    // Epilogue: c0,c1 -> (row g, cols 2t,2t+1); c2,c3 -> (row g+8)
#pragma unroll
    for (int mt = 0; mt < 2; ++mt)
#pragma unroll
        for (int nt = 0; nt < 4; ++nt) {
            int cc = n0 + wn + nt * 8 + t * 2;
            float2 bb = make_float2(0.f, 0.f);
            if (EPI >= 1) bb = *reinterpret_cast<const float2*>(bias + cc);
#pragma unroll
            for (int h = 0; h < 2; ++h) {
                int r = m0 + wm + mt * 16 + g + h * 8;
                float2 v = make_float2(d[mt][nt][h * 2 + 0], d[mt][nt][h * 2 + 1]);
                if (EPI >= 1) { v.x += bb.x; v.y += bb.y; }
                if (EPI == 2) {
                    v.x = to_tf32(fmaxf(v.x, 0.f)); v.y = to_tf32(fmaxf(v.y, 0.f));
                } else if (EPI == 3 || EPI == 4) {
                    const float* hp = Hbuf + (size_t)r * K2 + cc;
                    float2 h2  = *reinterpret_cast<const float2*>(hp);
                    float2 qi2 = *reinterpret_cast<const float2*>(hp + FF);
                    float a;
                    a = sigmoidf_(v.x); v.x = a * tanh_fast(qi2.x) + (1.f - a) * h2.x;
                    a = sigmoidf_(v.y); v.y = a * tanh_fast(qi2.y) + (1.f - a) * h2.y;
                    if (EPI == 3) { v.x = to_tf32(v.x); v.y = to_tf32(v.y); }
                }
                *reinterpret_cast<float2*>(C + (size_t)r * ldc + cc) = v;
            }
        }
}

// ------------------------- fused qi -------------------------
__global__ void __launch_bounds__(96) k_qi(const float* __restrict__ q) {
    int fb = blockIdx.x;
    int nq = blockIdx.y;
    int b  = blockIdx.z;
    int t  = threadIdx.x;
    int f  = fb * 96 + t;

    __shared__ float qs[LLQ * 96];
    float eq[LLQ];
#pragma unroll
    for (int l = 0; l < LLQ; ++l) {
        size_t qidx = ((size_t)(b * LLQ + l)) * FF + f;
        float qgv = g_QG[qidx];
        qgv = fminf(fmaxf(qgv, -60.f), 60.f);
        eq[l] = __expf(-qgv);
        qs[l * 96 + t] = q[qidx];
    }
    __syncthreads();

    int n0 = nq * 64;
    for (int n = n0; n < n0 + 64; ++n) {
        int node = b * 256 + n;
        float hgv = g_HG[(size_t)node * FF + f];
        hgv = fminf(fmaxf(hgv, -60.f), 60.f);
        float eh = __expf(-hgv);
        float acc = 0.f;
#pragma unroll
        for (int l = 0; l < LLQ; ++l) {
            float dd = fmaf(eh, eq[l], 1.0f);
            float s = __fdividef(1.0f, dd);
            acc = fmaf(s, qs[l * 96 + t], acc);
        }
        g_H[(size_t)node * K2 + FF + f] = to_tf32(acc);
    }
}

// ------------------------- host -------------------------
extern "C" void kernel_launch(void* const* d_in, const int* in_sizes, int n_in,
                              void* d_out, int out_size) {
    const float* x     = (const float*)d_in[0];
    const int*   ei    = (const int*)  d_in[1];
    const int*   et    = (const int*)  d_in[2];
    const float* q     = (const float*)d_in[3];
    const float* Wrel1 = (const float*)d_in[4];
    const float* Wrt1  = (const float*)d_in[5];
    const float* b1    = (const float*)d_in[6];
    const float* Wrel2 = (const float*)d_in[7];
    const float* Wrt2  = (const float*)d_in[8];
    const float* b2    = (const float*)d_in[9];
    const float* Wg    = (const float*)d_in[10];
    const float* bg    = (const float*)d_in[11];
    const float* Wq    = (const float*)d_in[12];
    const float* bq    = (const float*)d_in[13];
    float* out = (float*)d_out;

    float *pX4, *pWT, *pH, *pHG, *pQG, *pWgr, *pWqr, *pqr;
    cudaGetSymbolAddress((void**)&pX4,  g_X4);
    cudaGetSymbolAddress((void**)&pWT,  g_WcatT);
    cudaGetSymbolAddress((void**)&pH,   g_H);
    cudaGetSymbolAddress((void**)&pHG,  g_HG);
    cudaGetSymbolAddress((void**)&pQG,  g_QG);
    cudaGetSymbolAddress((void**)&pWgr, g_Wgr);
    cudaGetSymbolAddress((void**)&pWqr, g_Wqr);
    cudaGetSymbolAddress((void**)&pqr,  g_qr);

    cudaFuncSetAttribute(k_mma<0>, cudaFuncAttributeMaxDynamicSharedMemorySize, SMEM_MMA_BYTES);
    cudaFuncSetAttribute(k_mma<1>, cudaFuncAttributeMaxDynamicSharedMemorySize, SMEM_MMA_BYTES);
    cudaFuncSetAttribute(k_mma<2>, cudaFuncAttributeMaxDynamicSharedMemorySize, SMEM_MMA_BYTES);
    cudaFuncSetAttribute(k_mma<3>, cudaFuncAttributeMaxDynamicSharedMemorySize, SMEM_MMA_BYTES);
    cudaFuncSetAttribute(k_mma<4>, cudaFuncAttributeMaxDynamicSharedMemorySize, SMEM_MMA_BYTES);

    int nWg4 = FF * 2 * FF / 4, nq4 = BB * LLQ * FF / 4;
    dim3 gBig(FF / 64, BNN / 64);            // 12 x 32 = 384 CTAs
    dim3 gQg (FF / 64, (BB * LLQ) / 64);     // 12 x 8
    dim3 gTr (K4 / 32, FF / 32);
    dim3 bTr (32, 8);

    // ---- launches 1-4: rounds + qg GEMM (puts k_mma at the ncu-profiled slot) ----
    k_round4<<<(nWg4 + 255) / 256, 256>>>((const float4*)Wg, (float4*)pWgr, nWg4);
    k_round4<<<(nq4 + 255) / 256, 256>>>((const float4*)q, (float4*)pqr, nq4);
    k_round4<<<(nWg4 + 255) / 256, 256>>>((const float4*)Wq, (float4*)pWqr, nWg4);
    k_mma<1><<<gQg, 128, SMEM_MMA_BYTES>>>(pqr, FF, pWgr + FF, 2 * FF, pQG, FF, FF, bg, nullptr);

    // ---- CSR build ----
    k_zero_bins<<<(NBINS + 255) / 256, 256>>>();
    k_hist<<<EE / 256, 256>>>(ei, et);
    k_scan<<<1, 1024>>>();
    k_fill<<<EE / 256, 256>>>(ei, et);

    // ---- layer 1: RGCN ----
    k_copy_x<<<(BNN * 192 + 255) / 256, 256>>>((const float4*)x);
    k_transpose_w<<<gTr, bTr>>>(Wrt1, Wrel1);
    k_aggregate<<<NBINS, 192>>>();
    k_mma<2><<<gBig, 128, SMEM_MMA_BYTES>>>(pX4, K4, pWT, K4, pH, K2, K4, b1, nullptr);

    // ---- gate 1 ----
    k_mma<0><<<gBig, 128, SMEM_MMA_BYTES>>>(pH, K2, pWgr, 2 * FF, pHG, FF, FF, nullptr, nullptr);
    k_qi<<<dim3(8, 4, 8), 96>>>(q);
    k_mma<3><<<gBig, 128, SMEM_MMA_BYTES>>>(pH, K2, pWqr, 2 * FF, pX4, K4, K2, bq, pH);

    // ---- layer 2: RGCN ----
    k_transpose_w<<<gTr, bTr>>>(Wrt2, Wrel2);
    k_aggregate<<<NBINS, 192>>>();
    k_mma<2><<<gBig, 128, SMEM_MMA_BYTES>>>(pX4, K4, pWT, K4, pH, K2, K4, b2, nullptr);

    // ---- gate 2 ----
    k_mma<0><<<gBig, 128, SMEM_MMA_BYTES>>>(pH, K2, pWgr, 2 * FF, pHG, FF, FF, nullptr, nullptr);
    k_qi<<<dim3(8, 4, 8), 96>>>(q);
    k_mma<4><<<gBig, 128, SMEM_MMA_BYTES>>>(pH, K2, pWqr, 2 * FF, out, FF, K2, bq, pH);
}

// round 7
// speedup vs baseline: 2.3734x; 1.0066x over previous
#include <cuda_runtime.h>
#include <cstdint>
#include <math.h>

// Problem constants
#define BNN   2048
#define FF    768
#define EE    65536
#define BB    8
#define LLQ   64
#define NREL  3
#define NBINS (BNN*NREL)
#define K4    3072
#define K2    1536

// ------------------------- device scratch -------------------------
__device__ int   g_bin_cnt[NBINS];
__device__ int   g_bin_off[NBINS];
__device__ int   g_cursor[NBINS];
__device__ float g_inv_cnt[NBINS];
__device__ int   g_sorted_src[EE];
__device__ float g_X4[(size_t)BNN * K4];      // [x|agg0|agg1|agg2]  (tf32-rounded)
__device__ float g_WcatT[(size_t)FF * K4];    // transposed weights  (tf32-rounded)
__device__ float g_H[(size_t)BNN * K2];       // [h | qi]            (tf32-rounded)
__device__ float g_HG[(size_t)BNN * FF];      // hg (full fp32)
__device__ float g_QG[(size_t)BB * LLQ * FF]; // qg (full fp32)
__device__ float g_Wgr[(size_t)FF * 2 * FF];  // rounded Wg
__device__ float g_Wqr[(size_t)FF * 2 * FF];  // rounded Wq
__device__ float g_qr[(size_t)BB * LLQ * FF]; // rounded q
__device__ float g_P[(size_t)2 * BNN * FF];   // split-K partials [2][M][768]

__device__ __forceinline__ float sigmoidf_(float x) {
    return __fdividef(1.0f, 1.0f + __expf(-x));
}
__device__ __forceinline__ float tanh_fast(float x) {
    float e = __expf(2.0f * x);
    return 1.0f - __fdividef(2.0f, e + 1.0f);
}
__device__ __forceinline__ float to_tf32(float x) {
    uint32_t u;
    asm("cvt.rna.tf32.f32 %0, %1;" : "=r"(u) : "f"(x));
    return __uint_as_float(u);
}
__device__ __forceinline__ float4 r4(float4 v) {
    return make_float4(to_tf32(v.x), to_tf32(v.y), to_tf32(v.z), to_tf32(v.w));
}
__device__ __forceinline__ uint32_t smem_u32(const void* p) {
    uint32_t a;
    asm("{ .reg .u64 t; cvta.to.shared.u64 t, %1; cvt.u32.u64 %0, t; }" : "=r"(a) : "l"(p));
    return a;
}
__device__ __forceinline__ void cp16(uint32_t dst, const void* src) {
    asm volatile("cp.async.cg.shared.global [%0], [%1], 16;" :: "r"(dst), "l"(src));
}
#define CP_COMMIT() asm volatile("cp.async.commit_group;" ::: "memory")
#define CP_WAIT1()  asm volatile("cp.async.wait_group 1;" ::: "memory")
#define CP_WAIT0()  asm volatile("cp.async.wait_group 0;" ::: "memory")

#define MMA_TF32(D, Aa, Bb) \
    asm volatile("mma.sync.aligned.m16n8k8.row.col.f32.tf32.tf32.f32 " \
        "{%0,%1,%2,%3}, {%4,%5,%6,%7}, {%8,%9}, {%0,%1,%2,%3};" \
        : "+f"((D)[0]), "+f"((D)[1]), "+f"((D)[2]), "+f"((D)[3]) \
        : "r"((Aa)[0]), "r"((Aa)[1]), "r"((Aa)[2]), "r"((Aa)[3]), \
          "r"((Bb)[0]), "r"((Bb)[1]))

// Fragment load: af[2][4], bf[4][2] from padded smem tiles (ld 36)
#define LOAD_FRAGS(ksv, af, bf, As_, Bs_) do { \
    int _kc = (ksv) * 8 + t; \
    for (int _mt = 0; _mt < 2; ++_mt) { \
        int _r = wm + _mt * 16 + g; \
        (af)[_mt][0] = __float_as_uint((As_)[_r * 36 + _kc]); \
        (af)[_mt][1] = __float_as_uint((As_)[(_r + 8) * 36 + _kc]); \
        (af)[_mt][2] = __float_as_uint((As_)[_r * 36 + _kc + 4]); \
        (af)[_mt][3] = __float_as_uint((As_)[(_r + 8) * 36 + _kc + 4]); \
    } \
    for (int _nt = 0; _nt < 4; ++_nt) { \
        int _rn = wn + _nt * 8 + g; \
        (bf)[_nt][0] = __float_as_uint((Bs_)[_rn * 36 + _kc]); \
        (bf)[_nt][1] = __float_as_uint((Bs_)[_rn * 36 + _kc + 4]); \
    } \
} while (0)

// ------------------------- CSR build -------------------------
__global__ void k_zero_bins() {
    int i = blockIdx.x * blockDim.x + threadIdx.x;
    if (i < NBINS) g_bin_cnt[i] = 0;
}

__global__ void k_hist(const int* __restrict__ ei, const int* __restrict__ et) {
    int i = blockIdx.x * blockDim.x + threadIdx.x;
    if (i < EE) {
        int dst = ei[EE + i];
        atomicAdd(&g_bin_cnt[dst * NREL + et[i]], 1);
    }
}

__global__ void k_scan() {
    __shared__ int wsum[32];
    int t = threadIdx.x;
    int c[6], loc[6];
    int s = 0;
#pragma unroll
    for (int j = 0; j < 6; ++j) { c[j] = g_bin_cnt[t * 6 + j]; loc[j] = s; s += c[j]; }
    int lane = t & 31, w = t >> 5;
    int v = s;
#pragma unroll
    for (int d = 1; d < 32; d <<= 1) { int u = __shfl_up_sync(0xffffffffu, v, d); if (lane >= d) v += u; }
    if (lane == 31) wsum[w] = v;
    __syncthreads();
    if (w == 0) {
        int u = wsum[lane];
#pragma unroll
        for (int d = 1; d < 32; d <<= 1) { int z = __shfl_up_sync(0xffffffffu, u, d); if (lane >= d) u += z; }
        wsum[lane] = u;
    }
    __syncthreads();
    int base = (w > 0 ? wsum[w - 1] : 0) + (v - s);
#pragma unroll
    for (int j = 0; j < 6; ++j) {
        int idx = t * 6 + j;
        int off = base + loc[j];
        g_bin_off[idx] = off;
        g_cursor[idx]  = off;
        g_inv_cnt[idx] = 1.0f / (float)(c[j] > 0 ? c[j] : 1);
    }
}

__global__ void k_fill(const int* __restrict__ ei, const int* __restrict__ et) {
    int i = blockIdx.x * blockDim.x + threadIdx.x;
    if (i < EE) {
        int dst = ei[EE + i];
        int pos = atomicAdd(&g_cursor[dst * NREL + et[i]], 1);
        g_sorted_src[pos] = ei[i];
    }
}

// ------------------------- copies (tf32-rounding producers) -------------------------
__global__ void k_copy_x(const float4* __restrict__ src) {
    int i = blockIdx.x * blockDim.x + threadIdx.x;
    if (i < BNN * 192) {
        int row = i / 192, c = i - row * 192;
        reinterpret_cast<float4*>(g_X4)[(size_t)row * 768 + c] = r4(src[(size_t)row * 192 + c]);
    }
}

__global__ void k_round4(const float4* __restrict__ src, float4* __restrict__ dst, int n4) {
    int i = blockIdx.x * blockDim.x + threadIdx.x;
    if (i < n4) dst[i] = r4(src[i]);
}

// WcatT[n][k] = (k<768 ? Wroot[k][n] : Wrel_flat[k-768][n]); tiled transpose + round
__global__ void __launch_bounds__(256) k_transpose_w(
    const float* __restrict__ Wroot, const float* __restrict__ Wrel) {
    __shared__ float t[32][33];
    int kb = blockIdx.x * 32, nb = blockIdx.y * 32;
    int tx = threadIdx.x, ty = threadIdx.y;   // block (32, 8)
#pragma unroll
    for (int j = 0; j < 4; ++j) {
        int k = kb + ty + j * 8;
        float v = (k < FF) ? Wroot[(size_t)k * FF + nb + tx]
                           : Wrel[(size_t)(k - FF) * FF + nb + tx];
        t[ty + j * 8][tx] = to_tf32(v);
    }
    __syncthreads();
#pragma unroll
    for (int j = 0; j < 4; ++j) {
        int n = nb + ty + j * 8;
        g_WcatT[(size_t)n * K4 + kb + tx] = t[tx][ty + j * 8];
    }
}

// ------------------------- aggregation -------------------------
__global__ void __launch_bounds__(192) k_aggregate() {
    int bin = blockIdx.x;
    int dst = bin / NREL;
    int rel = bin - dst * NREL;
    int beg = g_bin_off[bin];
    int cnt = g_bin_cnt[bin];
    int t = threadIdx.x;
    const float4* x4 = reinterpret_cast<const float4*>(g_X4);
    float4 acc = make_float4(0.f, 0.f, 0.f, 0.f);
    int sNext = (cnt > 0) ? g_sorted_src[beg] : 0;
    for (int j = 0; j < cnt; ++j) {
        int s = sNext;
        if (j + 1 < cnt) sNext = g_sorted_src[beg + j + 1];
        float4 v = x4[(size_t)s * 768 + t];
        acc.x += v.x; acc.y += v.y; acc.z += v.z; acc.w += v.w;
    }
    float ic = g_inv_cnt[bin];
    acc.x *= ic; acc.y *= ic; acc.z *= ic; acc.w *= ic;
    reinterpret_cast<float4*>(g_X4)[(size_t)dst * 768 + (size_t)(rel + 1) * 192 + t] = r4(acc);
}

// ------------------------- split-K tf32 mma.sync GEMM -------------------------
// P[z][M][768] partial = A[M, kOff:kOff+Kh] @ B[:, kOff:kOff+Kh]^T
// CTA tile 64x64, K-chunk 32, 128 threads (4 warps, 32x32 each), 3-stage cp.async
// ring, 1 bar/chunk, register fragment double-buffering.
#define SM_STAGE 4608                 // floats per stage (2 x 64 x 36)
#define SMEM_MMA_BYTES (3 * SM_STAGE * 4)

__global__ void __launch_bounds__(128, 4) k_mma_sk(
    const float* __restrict__ A, int lda,
    const float* __restrict__ B, int ldb,
    float* __restrict__ P, int Kh)
{
    extern __shared__ float sm[];
    const int tid = threadIdx.x;
    const int m0 = blockIdx.y * 64;
    const int n0 = blockIdx.x * 64;
    const int Mtot = gridDim.y * 64;
    const int kOff = blockIdx.z * Kh;
    const int wid = tid >> 5, lane = tid & 31;
    const int wm = (wid >> 1) * 32;
    const int wn = (wid & 1) * 32;
    const int g = lane >> 2, t = lane & 3;
    const int lr = tid >> 3;          // 0..15
    const int lc = (tid & 7) * 4;     // 0..28

    const uint32_t smb = smem_u32(sm);
    const uint32_t soff = ((uint32_t)lr * 36 + (uint32_t)lc) * 4u;

    float d[2][4][4];
#pragma unroll
    for (int mt = 0; mt < 2; ++mt)
#pragma unroll
        for (int nt = 0; nt < 4; ++nt)
#pragma unroll
            for (int j = 0; j < 4; ++j) d[mt][nt][j] = 0.f;

    const int nk = Kh >> 5;
    const float* Abase = A + (size_t)(m0 + lr) * lda + kOff + lc;
    const float* Bbase = B + (size_t)(n0 + lr) * ldb + kOff + lc;

    auto issue = [&](int c, int s) {
        uint32_t as_ = smb + (uint32_t)s * (SM_STAGE * 4) + soff;
        uint32_t bs_ = as_ + 2304 * 4;
        int k0 = c << 5;
#pragma unroll
        for (int i = 0; i < 4; ++i) {
            cp16(as_ + (uint32_t)i * (16 * 36 * 4), Abase + (size_t)i * 16 * lda + k0);
            cp16(bs_ + (uint32_t)i * (16 * 36 * 4), Bbase + (size_t)i * 16 * ldb + k0);
        }
        CP_COMMIT();
    };

    issue(0, 0);
    if (nk > 1) issue(1, 1);

    int sIss = 2, sCur = 0;
    for (int c = 0; c < nk; ++c) {
        if (c + 1 < nk) CP_WAIT1(); else CP_WAIT0();
        __syncthreads();
        if (c + 2 < nk) { issue(c + 2, sIss); sIss = (sIss == 2) ? 0 : sIss + 1; }

        const float* As_ = sm + sCur * SM_STAGE;
        const float* Bs_ = As_ + 2304;
        sCur = (sCur == 2) ? 0 : sCur + 1;

        uint32_t afr[2][2][4], bfr[2][4][2];
        LOAD_FRAGS(0, afr[0], bfr[0], As_, Bs_);
#pragma unroll
        for (int ks = 0; ks < 4; ++ks) {
            int cur = ks & 1;
            if (ks < 3) LOAD_FRAGS(ks + 1, afr[cur ^ 1], bfr[cur ^ 1], As_, Bs_);
#pragma unroll
            for (int mt = 0; mt < 2; ++mt)
#pragma unroll
                for (int nt = 0; nt < 4; ++nt)
                    MMA_TF32(d[mt][nt], afr[cur][mt], bfr[cur][nt]);
        }
    }

    float* Cp = P + (size_t)blockIdx.z * Mtot * FF;
#pragma unroll
    for (int mt = 0; mt < 2; ++mt)
#pragma unroll
        for (int nt = 0; nt < 4; ++nt) {
            int cc = n0 + wn + nt * 8 + t * 2;
#pragma unroll
            for (int h = 0; h < 2; ++h) {
                int r = m0 + wm + mt * 16 + g + h * 8;
                float2 v = make_float2(d[mt][nt][h * 2 + 0], d[mt][nt][h * 2 + 1]);
                *reinterpret_cast<float2*>(Cp + (size_t)r * FF + cc) = v;
            }
        }
}

// ------------------------- split-K combine + fused epilogue -------------------------
// EPI: 0 none, 1 +bias, 2 relu(+bias)+round, 3 gate+round, 4 gate(no round)
template<int EPI>
__global__ void k_combine(const float* __restrict__ P, float* __restrict__ C, int ldc,
                          int Mtot, const float* __restrict__ bias,
                          const float* __restrict__ Hbuf) {
    int i = blockIdx.x * blockDim.x + threadIdx.x;   // over Mtot*192
    if (i >= Mtot * 192) return;
    int row = i / 192, c4 = i - row * 192;
    int col = c4 * 4;
    const float4* P4 = reinterpret_cast<const float4*>(P);
    float4 a = P4[(size_t)row * 192 + c4];
    float4 b = P4[(size_t)(Mtot + row) * 192 + c4];
    float4 v = make_float4(a.x + b.x, a.y + b.y, a.z + b.z, a.w + b.w);
    if (EPI >= 1) {
        float4 b4 = reinterpret_cast<const float4*>(bias)[c4];
        v.x += b4.x; v.y += b4.y; v.z += b4.z; v.w += b4.w;
    }
    if (EPI == 2) {
        v.x = to_tf32(fmaxf(v.x, 0.f)); v.y = to_tf32(fmaxf(v.y, 0.f));
        v.z = to_tf32(fmaxf(v.z, 0.f)); v.w = to_tf32(fmaxf(v.w, 0.f));
    } else if (EPI == 3 || EPI == 4) {
        const float* hp = Hbuf + (size_t)row * K2 + col;
        float4 h4  = *reinterpret_cast<const float4*>(hp);
        float4 qi4 = *reinterpret_cast<const float4*>(hp + FF);
        float al;
        al = sigmoidf_(v.x); v.x = al * tanh_fast(qi4.x) + (1.f - al) * h4.x;
        al = sigmoidf_(v.y); v.y = al * tanh_fast(qi4.y) + (1.f - al) * h4.y;
        al = sigmoidf_(v.z); v.z = al * tanh_fast(qi4.z) + (1.f - al) * h4.z;
        al = sigmoidf_(v.w); v.w = al * tanh_fast(qi4.w) + (1.f - al) * h4.w;
        if (EPI == 3) v = r4(v);
    }
    *reinterpret_cast<float4*>(C + (size_t)row * ldc + col) = v;
}

// ------------------------- fused qi -------------------------
__global__ void __launch_bounds__(96) k_qi(const float* __restrict__ q) {
    int fb = blockIdx.x;
    int nq = blockIdx.y;
    int b  = blockIdx.z;
    int t  = threadIdx.x;
    int f  = fb * 96 + t;

    __shared__ float qs[LLQ * 96];
    float eq[LLQ];
#pragma unroll
    for (int l = 0; l < LLQ; ++l) {
        size_t qidx = ((size_t)(b * LLQ + l)) * FF + f;
        float qgv = g_QG[qidx];
        qgv = fminf(fmaxf(qgv, -60.f), 60.f);
        eq[l] = __expf(-qgv);
        qs[l * 96 + t] = q[qidx];
    }
    __syncthreads();

    int n0 = nq * 64;
    for (int n = n0; n < n0 + 64; ++n) {
        int node = b * 256 + n;
        float hgv = g_HG[(size_t)node * FF + f];
        hgv = fminf(fmaxf(hgv, -60.f), 60.f);
        float eh = __expf(-hgv);
        float acc = 0.f;
#pragma unroll
        for (int l = 0; l < LLQ; ++l) {
            float dd = fmaf(eh, eq[l], 1.0f);
            float s = __fdividef(1.0f, dd);
            acc = fmaf(s, qs[l * 96 + t], acc);
        }
        g_H[(size_t)node * K2 + FF + f] = to_tf32(acc);
    }
}

// ------------------------- host -------------------------
extern "C" void kernel_launch(void* const* d_in, const int* in_sizes, int n_in,
                              void* d_out, int out_size) {
    const float* x     = (const float*)d_in[0];
    const int*   ei    = (const int*)  d_in[1];
    const int*   et    = (const int*)  d_in[2];
    const float* q     = (const float*)d_in[3];
    const float* Wrel1 = (const float*)d_in[4];
    const float* Wrt1  = (const float*)d_in[5];
    const float* b1    = (const float*)d_in[6];
    const float* Wrel2 = (const float*)d_in[7];
    const float* Wrt2  = (const float*)d_in[8];
    const float* b2    = (const float*)d_in[9];
    const float* Wg    = (const float*)d_in[10];
    const float* bg    = (const float*)d_in[11];
    const float* Wq    = (const float*)d_in[12];
    const float* bq    = (const float*)d_in[13];
    float* out = (float*)d_out;

    float *pX4, *pWT, *pH, *pHG, *pQG, *pWgr, *pWqr, *pqr, *pP;
    cudaGetSymbolAddress((void**)&pX4,  g_X4);
    cudaGetSymbolAddress((void**)&pWT,  g_WcatT);
    cudaGetSymbolAddress((void**)&pH,   g_H);
    cudaGetSymbolAddress((void**)&pHG,  g_HG);
    cudaGetSymbolAddress((void**)&pQG,  g_QG);
    cudaGetSymbolAddress((void**)&pWgr, g_Wgr);
    cudaGetSymbolAddress((void**)&pWqr, g_Wqr);
    cudaGetSymbolAddress((void**)&pqr,  g_qr);
    cudaGetSymbolAddress((void**)&pP,   g_P);

    cudaFuncSetAttribute(k_mma_sk, cudaFuncAttributeMaxDynamicSharedMemorySize, SMEM_MMA_BYTES);

    int nWg4 = FF * 2 * FF / 4, nq4 = BB * LLQ * FF / 4;
    dim3 gBig(FF / 64, BNN / 64, 2);         // 12 x 32 x 2 = 768 CTAs
    dim3 gQg (FF / 64, (BB * LLQ) / 64, 2);  // 12 x 8 x 2
    dim3 gTr (K4 / 32, FF / 32);
    dim3 bTr (32, 8);
    int cbBig = (BNN * 192 + 255) / 256;
    int cbQg  = (BB * LLQ * 192 + 255) / 256;

    // ---- launches 1-4: rounds + qg split-GEMM (k_mma_sk at ncu slot #4) ----
    k_round4<<<(nWg4 + 255) / 256, 256>>>((const float4*)Wg, (float4*)pWgr, nWg4);
    k_round4<<<(nq4 + 255) / 256, 256>>>((const float4*)q, (float4*)pqr, nq4);
    k_round4<<<(nWg4 + 255) / 256, 256>>>((const float4*)Wq, (float4*)pWqr, nWg4);
    k_mma_sk<<<gQg, 128, SMEM_MMA_BYTES>>>(pqr, FF, pWgr + FF, 2 * FF, pP, FF / 2);
    k_combine<1><<<cbQg, 256>>>(pP, pQG, FF, BB * LLQ, bg, nullptr);

    // ---- CSR build ----
    k_zero_bins<<<(NBINS + 255) / 256, 256>>>();
    k_hist<<<EE / 256, 256>>>(ei, et);
    k_scan<<<1, 1024>>>();
    k_fill<<<EE / 256, 256>>>(ei, et);

    // ---- layer 1: RGCN ----
    k_copy_x<<<(BNN * 192 + 255) / 256, 256>>>((const float4*)x);
    k_transpose_w<<<gTr, bTr>>>(Wrt1, Wrel1);
    k_aggregate<<<NBINS, 192>>>();
    k_mma_sk<<<gBig, 128, SMEM_MMA_BYTES>>>(pX4, K4, pWT, K4, pP, K4 / 2);
    k_combine<2><<<cbBig, 256>>>(pP, pH, K2, BNN, b1, nullptr);

    // ---- gate 1 ----
    // hg GEMM: total K = FF (h columns only!) -> Kh = FF/2
    k_mma_sk<<<gBig, 128, SMEM_MMA_BYTES>>>(pH, K2, pWgr, 2 * FF, pP, FF / 2);
    k_combine<0><<<cbBig, 256>>>(pP, pHG, FF, BNN, nullptr, nullptr);
    k_qi<<<dim3(8, 4, 8), 96>>>(q);
    k_mma_sk<<<gBig, 128, SMEM_MMA_BYTES>>>(pH, K2, pWqr, 2 * FF, pP, K2 / 2);
    k_combine<3><<<cbBig, 256>>>(pP, pX4, K4, BNN, bq, pH);

    // ---- layer 2: RGCN ----
    k_transpose_w<<<gTr, bTr>>>(Wrt2, Wrel2);
    k_aggregate<<<NBINS, 192>>>();
    k_mma_sk<<<gBig, 128, SMEM_MMA_BYTES>>>(pX4, K4, pWT, K4, pP, K4 / 2);
    k_combine<2><<<cbBig, 256>>>(pP, pH, K2, BNN, b2, nullptr);

    // ---- gate 2 ----
    k_mma_sk<<<gBig, 128, SMEM_MMA_BYTES>>>(pH, K2, pWgr, 2 * FF, pP, FF / 2);
    k_combine<0><<<cbBig, 256>>>(pP, pHG, FF, BNN, nullptr, nullptr);
    k_qi<<<dim3(8, 4, 8), 96>>>(q);
    k_mma_sk<<<gBig, 128, SMEM_MMA_BYTES>>>(pH, K2, pWqr, 2 * FF, pP, K2 / 2);
    k_combine<4><<<cbBig, 256>>>(pP, out, FF, BNN, bq, pH);
}

// round 8
// speedup vs baseline: 2.6550x; 1.1186x over previous
#include <cuda_runtime.h>
#include <cstdint>
#include <math.h>

// Problem constants
#define BNN   2048
#define FF    768
#define EE    65536
#define BB    8
#define LLQ   64
#define NREL  3
#define NBINS (BNN*NREL)
#define K4    3072
#define K2    1536

// ------------------------- device scratch -------------------------
__device__ int   g_bin_cnt[NBINS];
__device__ int   g_bin_off[NBINS];
__device__ int   g_cursor[NBINS];
__device__ float g_inv_cnt[NBINS];
__device__ int   g_sorted_src[EE];
__device__ float g_X4[(size_t)BNN * K4];      // [x|agg0|agg1|agg2]  (tf32-rounded)
__device__ float g_WcatT[(size_t)FF * K4];    // transposed weights  (tf32-rounded)
__device__ float g_H[(size_t)BNN * K2];       // [h | qi]            (tf32-rounded)
__device__ float g_Wgr[(size_t)FF * 2 * FF];  // rounded Wg
__device__ float g_Wqr[(size_t)FF * 2 * FF];  // rounded Wq
__device__ float g_qr[(size_t)BB * LLQ * FF]; // rounded q
__device__ float g_P[(size_t)2 * BNN * FF];   // split-K partials [2][2048][768]
__device__ float g_QGp[(size_t)2 * BB * LLQ * FF]; // qg partials [2][512][768]

__device__ __forceinline__ float sigmoidf_(float x) {
    return __fdividef(1.0f, 1.0f + __expf(-x));
}
__device__ __forceinline__ float tanh_fast(float x) {
    float e = __expf(2.0f * x);
    return 1.0f - __fdividef(2.0f, e + 1.0f);
}
__device__ __forceinline__ float to_tf32(float x) {
    uint32_t u;
    asm("cvt.rna.tf32.f32 %0, %1;" : "=r"(u) : "f"(x));
    return __uint_as_float(u);
}
__device__ __forceinline__ float4 r4(float4 v) {
    return make_float4(to_tf32(v.x), to_tf32(v.y), to_tf32(v.z), to_tf32(v.w));
}
__device__ __forceinline__ uint32_t smem_u32(const void* p) {
    uint32_t a;
    asm("{ .reg .u64 t; cvta.to.shared.u64 t, %1; cvt.u32.u64 %0, t; }" : "=r"(a) : "l"(p));
    return a;
}
__device__ __forceinline__ void cp16(uint32_t dst, const void* src) {
    asm volatile("cp.async.cg.shared.global [%0], [%1], 16;" :: "r"(dst), "l"(src));
}
#define CP_COMMIT() asm volatile("cp.async.commit_group;" ::: "memory")
#define CP_WAIT1()  asm volatile("cp.async.wait_group 1;" ::: "memory")
#define CP_WAIT0()  asm volatile("cp.async.wait_group 0;" ::: "memory")

#define MMA_TF32(D, Aa, b0v, b1v) \
    asm volatile("mma.sync.aligned.m16n8k8.row.col.f32.tf32.tf32.f32 " \
        "{%0,%1,%2,%3}, {%4,%5,%6,%7}, {%8,%9}, {%0,%1,%2,%3};" \
        : "+f"((D)[0]), "+f"((D)[1]), "+f"((D)[2]), "+f"((D)[3]) \
        : "r"((Aa)[0]), "r"((Aa)[1]), "r"((Aa)[2]), "r"((Aa)[3]), \
          "r"(b0v), "r"(b1v))

__device__ __forceinline__ void ldsm4(uint32_t addr, uint32_t* r) {
    asm volatile("ldmatrix.sync.aligned.m8n8.x4.shared.b16 {%0,%1,%2,%3}, [%4];"
        : "=r"(r[0]), "=r"(r[1]), "=r"(r[2]), "=r"(r[3]) : "r"(addr));
}

// ------------------------- CSR build -------------------------
__global__ void k_zero_bins() {
    int i = blockIdx.x * blockDim.x + threadIdx.x;
    if (i < NBINS) g_bin_cnt[i] = 0;
}

__global__ void k_hist(const int* __restrict__ ei, const int* __restrict__ et) {
    int i = blockIdx.x * blockDim.x + threadIdx.x;
    if (i < EE) {
        int dst = ei[EE + i];
        atomicAdd(&g_bin_cnt[dst * NREL + et[i]], 1);
    }
}

__global__ void k_scan() {
    __shared__ int wsum[32];
    int t = threadIdx.x;
    int c[6], loc[6];
    int s = 0;
#pragma unroll
    for (int j = 0; j < 6; ++j) { c[j] = g_bin_cnt[t * 6 + j]; loc[j] = s; s += c[j]; }
    int lane = t & 31, w = t >> 5;
    int v = s;
#pragma unroll
    for (int d = 1; d < 32; d <<= 1) { int u = __shfl_up_sync(0xffffffffu, v, d); if (lane >= d) v += u; }
    if (lane == 31) wsum[w] = v;
    __syncthreads();
    if (w == 0) {
        int u = wsum[lane];
#pragma unroll
        for (int d = 1; d < 32; d <<= 1) { int z = __shfl_up_sync(0xffffffffu, u, d); if (lane >= d) u += z; }
        wsum[lane] = u;
    }
    __syncthreads();
    int base = (w > 0 ? wsum[w - 1] : 0) + (v - s);
#pragma unroll
    for (int j = 0; j < 6; ++j) {
        int idx = t * 6 + j;
        int off = base + loc[j];
        g_bin_off[idx] = off;
        g_cursor[idx]  = off;
        g_inv_cnt[idx] = 1.0f / (float)(c[j] > 0 ? c[j] : 1);
    }
}

__global__ void k_fill(const int* __restrict__ ei, const int* __restrict__ et) {
    int i = blockIdx.x * blockDim.x + threadIdx.x;
    if (i < EE) {
        int dst = ei[EE + i];
        int pos = atomicAdd(&g_cursor[dst * NREL + et[i]], 1);
        g_sorted_src[pos] = ei[i];
    }
}

// ------------------------- fused prep: round Wg,Wq,q and copy/round x -------------------------
#define N_WG4 (FF * 2 * FF / 4)          // 294912
#define N_Q4  (BB * LLQ * FF / 4)        // 98304
#define N_X4  (BNN * FF / 4)             // 393216
#define N_PREP (2 * N_WG4 + N_Q4 + N_X4)

__global__ void k_prep(const float4* __restrict__ Wg, const float4* __restrict__ Wq,
                       const float4* __restrict__ q, const float4* __restrict__ x) {
    int i = blockIdx.x * blockDim.x + threadIdx.x;
    if (i >= N_PREP) return;
    if (i < N_WG4) {
        reinterpret_cast<float4*>(g_Wgr)[i] = r4(Wg[i]);
    } else if (i < 2 * N_WG4) {
        int j = i - N_WG4;
        reinterpret_cast<float4*>(g_Wqr)[j] = r4(Wq[j]);
    } else if (i < 2 * N_WG4 + N_Q4) {
        int j = i - 2 * N_WG4;
        reinterpret_cast<float4*>(g_qr)[j] = r4(q[j]);
    } else {
        int j = i - 2 * N_WG4 - N_Q4;
        int row = j / 192, c = j - row * 192;
        reinterpret_cast<float4*>(g_X4)[(size_t)row * 768 + c] = r4(x[j]);
    }
}

// WcatT[n][k] = (k<768 ? Wroot[k][n] : Wrel_flat[k-768][n]); tiled transpose + round
__global__ void __launch_bounds__(256) k_transpose_w(
    const float* __restrict__ Wroot, const float* __restrict__ Wrel) {
    __shared__ float t[32][33];
    int kb = blockIdx.x * 32, nb = blockIdx.y * 32;
    int tx = threadIdx.x, ty = threadIdx.y;   // block (32, 8)
#pragma unroll
    for (int j = 0; j < 4; ++j) {
        int k = kb + ty + j * 8;
        float v = (k < FF) ? Wroot[(size_t)k * FF + nb + tx]
                           : Wrel[(size_t)(k - FF) * FF + nb + tx];
        t[ty + j * 8][tx] = to_tf32(v);
    }
    __syncthreads();
#pragma unroll
    for (int j = 0; j < 4; ++j) {
        int n = nb + ty + j * 8;
        g_WcatT[(size_t)n * K4 + kb + tx] = t[tx][ty + j * 8];
    }
}

// ------------------------- aggregation -------------------------
__global__ void __launch_bounds__(192) k_aggregate() {
    int bin = blockIdx.x;
    int dst = bin / NREL;
    int rel = bin - dst * NREL;
    int beg = g_bin_off[bin];
    int cnt = g_bin_cnt[bin];
    int t = threadIdx.x;
    const float4* x4 = reinterpret_cast<const float4*>(g_X4);
    float4 acc = make_float4(0.f, 0.f, 0.f, 0.f);
    int sNext = (cnt > 0) ? g_sorted_src[beg] : 0;
    for (int j = 0; j < cnt; ++j) {
        int s = sNext;
        if (j + 1 < cnt) sNext = g_sorted_src[beg + j + 1];
        float4 v = x4[(size_t)s * 768 + t];
        acc.x += v.x; acc.y += v.y; acc.z += v.z; acc.w += v.w;
    }
    float ic = g_inv_cnt[bin];
    acc.x *= ic; acc.y *= ic; acc.z *= ic; acc.w *= ic;
    reinterpret_cast<float4*>(g_X4)[(size_t)dst * 768 + (size_t)(rel + 1) * 192 + t] = r4(acc);
}

// ------------------------- split-K tf32 mma.sync GEMM (ldmatrix frags) ---------
// P[z][M][768] partial = A[M, kOff:kOff+Kh] @ B[:, kOff:kOff+Kh]^T
// CTA tile 64x64, K-chunk 32, 128 threads (4 warps, 32x32 each), 3-stage cp.async
// ring, 1 bar/chunk. Fragments via ldmatrix.x4.b16 (b32 tiles as b16 pairs).
#define SM_STAGE 4608                 // floats per stage (2 x 64 x 36)
#define STAGE_BYTES (SM_STAGE * 4)
#define SMEM_MMA_BYTES (3 * STAGE_BYTES)

__global__ void __launch_bounds__(128, 4) k_mma_sk(
    const float* __restrict__ A, int lda,
    const float* __restrict__ B, int ldb,
    float* __restrict__ P, int Kh)
{
    extern __shared__ float sm[];
    const int tid = threadIdx.x;
    const int m0 = blockIdx.y * 64;
    const int n0 = blockIdx.x * 64;
    const int Mtot = gridDim.y * 64;
    const int kOff = blockIdx.z * Kh;
    const int wid = tid >> 5, lane = tid & 31;
    const int wm = (wid >> 1) * 32;
    const int wn = (wid & 1) * 32;
    const int g = lane >> 2, t = lane & 3;
    const int lr = tid >> 3;          // 0..15
    const int lc = (tid & 7) * 4;     // 0..28

    const uint32_t smb = smem_u32(sm);
    const uint32_t soff = ((uint32_t)lr * 36 + (uint32_t)lc) * 4u;

    // ldmatrix lane-address offsets (bytes within a stage)
    const int l7 = lane & 7, l8 = (lane >> 3) & 1, l16 = (lane >> 4) & 1;
    const uint32_t aOff = ((uint32_t)(wm + l7 + l8 * 8) * 36 + (uint32_t)(l16 * 4)) * 4u;
    const uint32_t bOff = ((uint32_t)(wn + l7 + l16 * 8) * 36 + (uint32_t)(l8 * 4)) * 4u
                          + 2304u * 4u;   // B tile follows A tile in the stage

    float d[2][4][4];
#pragma unroll
    for (int mt = 0; mt < 2; ++mt)
#pragma unroll
        for (int nt = 0; nt < 4; ++nt)
#pragma unroll
            for (int j = 0; j < 4; ++j) d[mt][nt][j] = 0.f;

    const int nk = Kh >> 5;
    const float* Abase = A + (size_t)(m0 + lr) * lda + kOff + lc;
    const float* Bbase = B + (size_t)(n0 + lr) * ldb + kOff + lc;

    auto issue = [&](int c, int s) {
        uint32_t as_ = smb + (uint32_t)s * STAGE_BYTES + soff;
        uint32_t bs_ = as_ + 2304 * 4;
        int k0 = c << 5;
#pragma unroll
        for (int i = 0; i < 4; ++i) {
            cp16(as_ + (uint32_t)i * (16 * 36 * 4), Abase + (size_t)i * 16 * lda + k0);
            cp16(bs_ + (uint32_t)i * (16 * 36 * 4), Bbase + (size_t)i * 16 * ldb + k0);
        }
        CP_COMMIT();
    };

    issue(0, 0);
    if (nk > 1) issue(1, 1);

    int sIss = 2, sCur = 0;
    for (int c = 0; c < nk; ++c) {
        if (c + 1 < nk) CP_WAIT1(); else CP_WAIT0();
        __syncthreads();
        if (c + 2 < nk) { issue(c + 2, sIss); sIss = (sIss == 2) ? 0 : sIss + 1; }

        uint32_t stBase = smb + (uint32_t)sCur * STAGE_BYTES;
        sCur = (sCur == 2) ? 0 : sCur + 1;
        uint32_t aA0 = stBase + aOff;            // A, mt=0
        uint32_t aA1 = aA0 + 16 * 144;           // A, mt=1 (16 rows * 144B)
        uint32_t bA0 = stBase + bOff;            // B, nt pair 0 (nt=0,1)
        uint32_t bA1 = bA0 + 16 * 144;           // B, nt pair 1 (nt=2,3)

        // frag double buffer: aF[buf][mt][4], bF[buf][pair][4]
        uint32_t aF[2][2][4], bF[2][2][4];
        ldsm4(aA0, aF[0][0]); ldsm4(aA1, aF[0][1]);
        ldsm4(bA0, bF[0][0]); ldsm4(bA1, bF[0][1]);
#pragma unroll
        for (int ks = 0; ks < 4; ++ks) {
            int cur = ks & 1;
            if (ks < 3) {
                uint32_t off = (uint32_t)(ks + 1) * 32;
                ldsm4(aA0 + off, aF[cur ^ 1][0]); ldsm4(aA1 + off, aF[cur ^ 1][1]);
                ldsm4(bA0 + off, bF[cur ^ 1][0]); ldsm4(bA1 + off, bF[cur ^ 1][1]);
            }
#pragma unroll
            for (int mt = 0; mt < 2; ++mt)
#pragma unroll
                for (int p = 0; p < 2; ++p) {
                    MMA_TF32(d[mt][2 * p],     aF[cur][mt], bF[cur][p][0], bF[cur][p][1]);
                    MMA_TF32(d[mt][2 * p + 1], aF[cur][mt], bF[cur][p][2], bF[cur][p][3]);
                }
        }
    }

    float* Cp = P + (size_t)blockIdx.z * Mtot * FF;
#pragma unroll
    for (int mt = 0; mt < 2; ++mt)
#pragma unroll
        for (int nt = 0; nt < 4; ++nt) {
            int cc = n0 + wn + nt * 8 + t * 2;
#pragma unroll
            for (int h = 0; h < 2; ++h) {
                int r = m0 + wm + mt * 16 + g + h * 8;
                float2 v = make_float2(d[mt][nt][h * 2 + 0], d[mt][nt][h * 2 + 1]);
                *reinterpret_cast<float2*>(Cp + (size_t)r * FF + cc) = v;
            }
        }
}

// ------------------------- split-K combine + fused epilogue -------------------------
// EPI: 2 relu(+bias)+round, 3 gate+round, 4 gate(no round)
template<int EPI>
__global__ void k_combine(const float* __restrict__ P, float* __restrict__ C, int ldc,
                          int Mtot, const float* __restrict__ bias,
                          const float* __restrict__ Hbuf) {
    int i = blockIdx.x * blockDim.x + threadIdx.x;   // over Mtot*192
    if (i >= Mtot * 192) return;
    int row = i / 192, c4 = i - row * 192;
    int col = c4 * 4;
    const float4* P4 = reinterpret_cast<const float4*>(P);
    float4 a = P4[(size_t)row * 192 + c4];
    float4 b = P4[(size_t)(Mtot + row) * 192 + c4];
    float4 v = make_float4(a.x + b.x, a.y + b.y, a.z + b.z, a.w + b.w);
    float4 b4 = reinterpret_cast<const float4*>(bias)[c4];
    v.x += b4.x; v.y += b4.y; v.z += b4.z; v.w += b4.w;
    if (EPI == 2) {
        v.x = to_tf32(fmaxf(v.x, 0.f)); v.y = to_tf32(fmaxf(v.y, 0.f));
        v.z = to_tf32(fmaxf(v.z, 0.f)); v.w = to_tf32(fmaxf(v.w, 0.f));
    } else {
        const float* hp = Hbuf + (size_t)row * K2 + col;
        float4 h4  = *reinterpret_cast<const float4*>(hp);
        float4 qi4 = *reinterpret_cast<const float4*>(hp + FF);
        float al;
        al = sigmoidf_(v.x); v.x = al * tanh_fast(qi4.x) + (1.f - al) * h4.x;
        al = sigmoidf_(v.y); v.y = al * tanh_fast(qi4.y) + (1.f - al) * h4.y;
        al = sigmoidf_(v.z); v.z = al * tanh_fast(qi4.z) + (1.f - al) * h4.z;
        al = sigmoidf_(v.w); v.w = al * tanh_fast(qi4.w) + (1.f - al) * h4.w;
        if (EPI == 3) v = r4(v);
    }
    *reinterpret_cast<float4*>(C + (size_t)row * ldc + col) = v;
}

// ------------------------- fused qi (consumes hg & qg split-K partials) ------------
// qi[b,n,f] = sum_l sigmoid(hg + qg) * q; hg = P0+P1, qg = QGp0+QGp1+bg.
__global__ void __launch_bounds__(96) k_qi(const float* __restrict__ q,
                                           const float* __restrict__ bg) {
    int fb = blockIdx.x;
    int nq = blockIdx.y;
    int b  = blockIdx.z;
    int t  = threadIdx.x;
    int f  = fb * 96 + t;

    __shared__ float qs[LLQ * 96];
    float eq[LLQ];
    float bgv = bg[f];
#pragma unroll
    for (int l = 0; l < LLQ; ++l) {
        size_t qidx = ((size_t)(b * LLQ + l)) * FF + f;
        float qgv = g_QGp[qidx] + g_QGp[(size_t)BB * LLQ * FF + qidx] + bgv;
        qgv = fminf(fmaxf(qgv, -60.f), 60.f);
        eq[l] = __expf(-qgv);
        qs[l * 96 + t] = q[qidx];
    }
    __syncthreads();

    int n0 = nq * 64;
    for (int n = n0; n < n0 + 64; ++n) {
        int node = b * 256 + n;
        size_t hidx = (size_t)node * FF + f;
        float hgv = g_P[hidx] + g_P[(size_t)BNN * FF + hidx];
        hgv = fminf(fmaxf(hgv, -60.f), 60.f);
        float eh = __expf(-hgv);
        float acc = 0.f;
#pragma unroll
        for (int l = 0; l < LLQ; ++l) {
            float dd = fmaf(eh, eq[l], 1.0f);
            float s = __fdividef(1.0f, dd);
            acc = fmaf(s, qs[l * 96 + t], acc);
        }
        g_H[(size_t)node * K2 + FF + f] = to_tf32(acc);
    }
}

// ------------------------- host -------------------------
extern "C" void kernel_launch(void* const* d_in, const int* in_sizes, int n_in,
                              void* d_out, int out_size) {
    const float* x     = (const float*)d_in[0];
    const int*   ei    = (const int*)  d_in[1];
    const int*   et    = (const int*)  d_in[2];
    const float* q     = (const float*)d_in[3];
    const float* Wrel1 = (const float*)d_in[4];
    const float* Wrt1  = (const float*)d_in[5];
    const float* b1    = (const float*)d_in[6];
    const float* Wrel2 = (const float*)d_in[7];
    const float* Wrt2  = (const float*)d_in[8];
    const float* b2    = (const float*)d_in[9];
    const float* Wg    = (const float*)d_in[10];
    const float* bg    = (const float*)d_in[11];
    const float* Wq    = (const float*)d_in[12];
    const float* bq    = (const float*)d_in[13];
    float* out = (float*)d_out;

    float *pX4, *pWT, *pH, *pWgr, *pWqr, *pqr, *pP, *pQGp;
    cudaGetSymbolAddress((void**)&pX4,  g_X4);
    cudaGetSymbolAddress((void**)&pWT,  g_WcatT);
    cudaGetSymbolAddress((void**)&pH,   g_H);
    cudaGetSymbolAddress((void**)&pWgr, g_Wgr);
    cudaGetSymbolAddress((void**)&pWqr, g_Wqr);
    cudaGetSymbolAddress((void**)&pqr,  g_qr);
    cudaGetSymbolAddress((void**)&pP,   g_P);
    cudaGetSymbolAddress((void**)&pQGp, g_QGp);

    cudaFuncSetAttribute(k_mma_sk, cudaFuncAttributeMaxDynamicSharedMemorySize, SMEM_MMA_BYTES);

    dim3 gBig(FF / 64, BNN / 64, 2);         // 12 x 32 x 2 = 768 CTAs
    dim3 gQg (FF / 64, (BB * LLQ) / 64, 2);  // 12 x 8 x 2
    dim3 gTr (K4 / 32, FF / 32);
    dim3 bTr (32, 8);
    int cbBig = (BNN * 192 + 255) / 256;

    // 1: fused prep; 2-3: CSR start; 4: qg GEMM (ncu-profiled slot)
    k_prep<<<(N_PREP + 255) / 256, 256>>>((const float4*)Wg, (const float4*)Wq,
                                          (const float4*)q, (const float4*)x);
    k_zero_bins<<<(NBINS + 255) / 256, 256>>>();
    k_hist<<<EE / 256, 256>>>(ei, et);
    k_mma_sk<<<gQg, 128, SMEM_MMA_BYTES>>>(pqr, FF, pWgr + FF, 2 * FF, pQGp, FF / 2);
    k_scan<<<1, 1024>>>();
    k_fill<<<EE / 256, 256>>>(ei, et);

    // ---- layer 1: RGCN ----
    k_transpose_w<<<gTr, bTr>>>(Wrt1, Wrel1);
    k_aggregate<<<NBINS, 192>>>();
    k_mma_sk<<<gBig, 128, SMEM_MMA_BYTES>>>(pX4, K4, pWT, K4, pP, K4 / 2);
    k_combine<2><<<cbBig, 256>>>(pP, pH, K2, BNN, b1, nullptr);

    // ---- gate 1 ----
    k_mma_sk<<<gBig, 128, SMEM_MMA_BYTES>>>(pH, K2, pWgr, 2 * FF, pP, FF / 2);  // hg partials
    k_qi<<<dim3(8, 4, 8), 96>>>(q, bg);
    k_mma_sk<<<gBig, 128, SMEM_MMA_BYTES>>>(pH, K2, pWqr, 2 * FF, pP, K2 / 2);
    k_combine<3><<<cbBig, 256>>>(pP, pX4, K4, BNN, bq, pH);

    // ---- layer 2: RGCN ----
    k_transpose_w<<<gTr, bTr>>>(Wrt2, Wrel2);
    k_aggregate<<<NBINS, 192>>>();
    k_mma_sk<<<gBig, 128, SMEM_MMA_BYTES>>>(pX4, K4, pWT, K4, pP, K4 / 2);
    k_combine<2><<<cbBig, 256>>>(pP, pH, K2, BNN, b2, nullptr);

    // ---- gate 2 ----
    k_mma_sk<<<gBig, 128, SMEM_MMA_BYTES>>>(pH, K2, pWgr, 2 * FF, pP, FF / 2);  // hg partials
    k_qi<<<dim3(8, 4, 8), 96>>>(q, bg);
    k_mma_sk<<<gBig, 128, SMEM_MMA_BYTES>>>(pH, K2, pWqr, 2 * FF, pP, K2 / 2);
    k_combine<4><<<cbBig, 256>>>(pP, out, FF, BNN, bq, pH);
}